// round 6
// baseline (speedup 1.0000x reference)
#include <cuda_runtime.h>
#include <cuda_fp16.h>
#include <cstdint>

typedef unsigned long long u64;

namespace {
constexpr int B_ = 256, T_ = 128, SD_ = 8, AD_ = 2, H_ = 3, K_ = 4, HID_ = 256;
constexpr int QD_ = SD_ + AD_;    // 10
constexpr int HK_ = H_ * K_;      // 12
constexpr int FEAT_ = HK_ + QD_;  // 22
constexpr int MT_ = 64;           // tokens per CTA = half batch
constexpr int KP_ = 32;           // K panel
constexpr int NPAN_ = HID_ / KP_; // 8
constexpr int ASTRIDE = 264;      // fp16 elems per A row (256 + 8 pad) -> 528B
constexpr float WSCALE = 64.f;
constexpr float INVWS = 1.f / 64.f;
}

// W2*64 split into fp16 hi/lo
__device__ __half g_W2hi[HID_ * HID_];
__device__ __half g_W2lo[HID_ * HID_];

// ---------------- helpers ----------------
__device__ __forceinline__ u64 fma2(u64 a, u64 b, u64 c) {
    u64 d;
    asm("fma.rn.f32x2 %0, %1, %2, %3;" : "=l"(d) : "l"(a), "l"(b), "l"(c));
    return d;
}
__device__ __forceinline__ float2 u2f(u64 v) {
    float2 r;
    asm("mov.b64 {%0,%1}, %2;" : "=f"(r.x), "=f"(r.y) : "l"(v));
    return r;
}
__device__ __forceinline__ uint32_t smem_u32(const void* p) {
    uint32_t a;
    asm("{ .reg .u64 t; cvta.to.shared.u64 t, %1; cvt.u32.u64 %0, t; }" : "=r"(a) : "l"(p));
    return a;
}
__device__ __forceinline__ void ldsm4(uint32_t r[4], uint32_t addr) {
    asm volatile("ldmatrix.sync.aligned.m8n8.x4.shared.b16 {%0,%1,%2,%3}, [%4];"
                 : "=r"(r[0]), "=r"(r[1]), "=r"(r[2]), "=r"(r[3]) : "r"(addr));
}
__device__ __forceinline__ void mma16816(float c[4], const uint32_t a[4],
                                         uint32_t b0, uint32_t b1) {
    asm volatile(
        "mma.sync.aligned.m16n8k16.row.col.f32.f16.f16.f32 "
        "{%0,%1,%2,%3}, {%4,%5,%6,%7}, {%8,%9}, {%0,%1,%2,%3};"
        : "+f"(c[0]), "+f"(c[1]), "+f"(c[2]), "+f"(c[3])
        : "r"(a[0]), "r"(a[1]), "r"(a[2]), "r"(a[3]), "r"(b0), "r"(b1));
}
__device__ __forceinline__ void cp_async16(uint32_t dst, const void* src) {
    asm volatile("cp.async.ca.shared.global [%0], [%1], 16;" :: "r"(dst), "l"(src) : "memory");
}

// ---------------------------------------------------------------------------
// Kernel W: W2*64 -> fp16 hi/lo residual pair
// ---------------------------------------------------------------------------
__global__ __launch_bounds__(256) void w2split_kernel(const float* __restrict__ W2) {
    const int i = blockIdx.x * 256 + threadIdx.x;
    const float w = W2[i] * WSCALE;
    const __half hi = __float2half_rn(w);
    g_W2hi[i] = hi;
    g_W2lo[i] = __float2half_rn(w - __half2float(hi));
}

// ---------------------------------------------------------------------------
// Fused kernel: CTA = (batch, half): 64 tokens, 256 threads, 2 CTAs/SM.
//   phase 0: attention; K/V of all 128 batch tokens in smem; jj-loop split
//            4-way interleaved (jj = tsub + 4*jx) -> conflict-free sK reads.
//   phase 1: h1 = relu(feat@W1.T+b1) -> fp16 A tile [64][264].
//   phase 2: HMMA D = A@(64*W2)hi^T + A@(64*W2)lo^T, 8 K-panels of 32,
//            double-buffered via cp.async, 64B rows + XOR-16B swizzle.
//   epilogue: h2 = D/64 + b2; relu; dot Wout; reduce; +bout.
// ---------------------------------------------------------------------------
__global__ __launch_bounds__(256, 2) void fused_kernel(
    const float* __restrict__ state, const float* __restrict__ action,
    const float* __restrict__ Wk, const float* __restrict__ Wq,
    const float* __restrict__ Wv,
    const float* __restrict__ W1, const float* __restrict__ b1,
    const float* __restrict__ b2, const float* __restrict__ Wout,
    const float* __restrict__ bout, float* __restrict__ out)
{
    extern __shared__ char smem[];
    constexpr int ABYTES = MT_ * ASTRIDE * 2;          // 33792
    constexpr int OFF_A  = 0;
    constexpr int OFF_B  = ABYTES;
    constexpr int BPANEL = HID_ * KP_ * 2;             // 16384 (one hi or lo panel)
    constexpr int BUFSZ  = 2 * BPANEL;                 // 32768 (hi+lo)
    constexpr int OFF_F  = OFF_B + 2 * BUFSZ;          // feat [64][22] f32 = 5632
    constexpr int OFF_BW = OFF_F + MT_ * FEAT_ * 4;    // float2 x 256 = 2048
    constexpr int OFF_RED = OFF_BW + 2048;             // float x 64
    // aliases inside A region (dead once phase 1 starts)
    constexpr int OFF_SK = 0;                          // float [128][12] = 6144
    constexpr int OFF_SV = 6144;                       // 6144
    constexpr int OFF_PART = 12288;                    // float [3][15][64] = 11520

    const uint32_t sb = smem_u32(smem);
    const int tid = threadIdx.x, wid = tid >> 5, ln = tid & 31;
    const int b = blockIdx.x >> 1, half = blockIdx.x & 1;
    const int tok0 = half * MT_;   // token offset within batch

    float* sF = (float*)(smem + OFF_F);
    float2* sBW = (float2*)(smem + OFF_BW);
    float* sred = (float*)(smem + OFF_RED);
    float (*sK)[HK_] = (float(*)[HK_])(smem + OFF_SK);
    float (*sV)[HK_] = (float(*)[HK_])(smem + OFF_SV);
    float* sPART = (float*)(smem + OFF_PART);

    // ---- stage B panel p into buffer buf (swizzled 64B rows) ----
    auto stageB = [&](int p, int buf) {
        for (int it = tid; it < 2048; it += 256) {
            const int row = it >> 3, rem = it & 7, c = rem >> 1, hl = rem & 1;
            const uint32_t dst = sb + OFF_B + (uint32_t)(buf * BUFSZ + hl * BPANEL +
                                 row * 64 + (((c ^ ((row >> 1) & 3))) << 4));
            const __half* src = (hl ? g_W2lo : g_W2hi) + row * HID_ + p * KP_ + c * 8;
            cp_async16(dst, src);
        }
        asm volatile("cp.async.commit_group;" ::: "memory");
    };
    stageB(0, 0);  // prefetch panel 0 before attention

    sBW[tid] = make_float2(b2[tid], Wout[tid]);
    if (tid < MT_) sred[tid] = 0.f;

    // ---- phase 0: attention ----
    const int t_loc = tid >> 2, tsub = tid & 3;
    // K/V projections for all 128 batch tokens (state[:4] only)
    if (tid < T_) {
        const float4 s4 = *(const float4*)(state + (size_t)(b * T_ + tid) * SD_);
#pragma unroll
        for (int i = 0; i < HK_; i++) {
            sK[tid][i] = s4.x * Wk[i * 4] + s4.y * Wk[i * 4 + 1] +
                         s4.z * Wk[i * 4 + 2] + s4.w * Wk[i * 4 + 3];
            sV[tid][i] = s4.x * Wv[i * 4] + s4.y * Wv[i * 4 + 1] +
                         s4.z * Wv[i * 4 + 2] + s4.w * Wv[i * 4 + 3];
        }
    }
    // q for own token
    float q[HK_];
    {
        const int tg = b * T_ + tok0 + t_loc;
        const float* st = state + (size_t)tg * SD_;
        const float* ac = action + (size_t)tg * AD_;
        float qs[QD_];
#pragma unroll
        for (int c = 0; c < SD_; c++) qs[c] = st[c];
        qs[SD_] = ac[0];
        qs[SD_ + 1] = ac[1];
#pragma unroll
        for (int i = 0; i < HK_; i++) {
            float a = 0.f;
#pragma unroll
            for (int c = 0; c < QD_; c++) a = fmaf(qs[c], Wq[i * QD_ + c], a);
            q[i] = a;
        }
        if (tsub == 0) {
            float* fo = sF + t_loc * FEAT_;
#pragma unroll
            for (int c = 0; c < QD_; c++) fo[HK_ + c] = qs[c];
        }
    }
    __syncthreads();

    {
        float sum0 = 0.f, sum1 = 0.f, sum2 = 0.f;
        float acc[HK_];
#pragma unroll
        for (int i = 0; i < HK_; i++) acc[i] = 0.f;
#pragma unroll 4
        for (int jx = 0; jx < 32; jx++) {
            const int jj = tsub + 4 * jx;  // interleaved: 4 rows/warp on distinct banks
            const float4 k0 = *(const float4*)&sK[jj][0];
            const float4 k1 = *(const float4*)&sK[jj][4];
            const float4 k2 = *(const float4*)&sK[jj][8];
            float s0 = q[0]*k0.x + q[1]*k0.y + q[2]*k0.z + q[3]*k0.w;
            float s1 = q[4]*k1.x + q[5]*k1.y + q[6]*k1.z + q[7]*k1.w;
            float s2 = q[8]*k2.x + q[9]*k2.y + q[10]*k2.z + q[11]*k2.w;
            const float e0 = __expf(0.5f * s0);
            const float e1 = __expf(0.5f * s1);
            const float e2 = __expf(0.5f * s2);
            sum0 += e0; sum1 += e1; sum2 += e2;
            const float4 v0 = *(const float4*)&sV[jj][0];
            const float4 v1 = *(const float4*)&sV[jj][4];
            const float4 v2 = *(const float4*)&sV[jj][8];
            acc[0]  = fmaf(e0, v0.x, acc[0]);  acc[1]  = fmaf(e0, v0.y, acc[1]);
            acc[2]  = fmaf(e0, v0.z, acc[2]);  acc[3]  = fmaf(e0, v0.w, acc[3]);
            acc[4]  = fmaf(e1, v1.x, acc[4]);  acc[5]  = fmaf(e1, v1.y, acc[5]);
            acc[6]  = fmaf(e1, v1.z, acc[6]);  acc[7]  = fmaf(e1, v1.w, acc[7]);
            acc[8]  = fmaf(e2, v2.x, acc[8]);  acc[9]  = fmaf(e2, v2.y, acc[9]);
            acc[10] = fmaf(e2, v2.z, acc[10]); acc[11] = fmaf(e2, v2.w, acc[11]);
        }
        if (tsub) {
            float* pp = sPART + (tsub - 1) * 15 * MT_ + t_loc;
            pp[0] = sum0; pp[64] = sum1; pp[128] = sum2;
#pragma unroll
            for (int i = 0; i < HK_; i++) pp[(3 + i) * 64] = acc[i];
        }
        __syncthreads();
        if (tsub == 0) {
#pragma unroll
            for (int s = 0; s < 3; s++) {
                const float* pp = sPART + s * 15 * MT_ + t_loc;
                sum0 += pp[0]; sum1 += pp[64]; sum2 += pp[128];
#pragma unroll
                for (int i = 0; i < HK_; i++) acc[i] += pp[(3 + i) * 64];
            }
            // subtract self (jj == tok0 + t_loc)
            const int ts = tok0 + t_loc;
            const float4 k0 = *(const float4*)&sK[ts][0];
            const float4 k1 = *(const float4*)&sK[ts][4];
            const float4 k2 = *(const float4*)&sK[ts][8];
            float s0 = q[0]*k0.x + q[1]*k0.y + q[2]*k0.z + q[3]*k0.w;
            float s1 = q[4]*k1.x + q[5]*k1.y + q[6]*k1.z + q[7]*k1.w;
            float s2 = q[8]*k2.x + q[9]*k2.y + q[10]*k2.z + q[11]*k2.w;
            const float e0 = __expf(0.5f * s0);
            const float e1 = __expf(0.5f * s1);
            const float e2 = __expf(0.5f * s2);
            sum0 -= e0; sum1 -= e1; sum2 -= e2;
            const float4 v0 = *(const float4*)&sV[ts][0];
            const float4 v1 = *(const float4*)&sV[ts][4];
            const float4 v2 = *(const float4*)&sV[ts][8];
            const float vp[HK_] = {v0.x, v0.y, v0.z, v0.w, v1.x, v1.y, v1.z, v1.w,
                                   v2.x, v2.y, v2.z, v2.w};
            const float i0 = 1.f / sum0, i1 = 1.f / sum1, i2 = 1.f / sum2;
            float* fo = sF + t_loc * FEAT_;
#pragma unroll
            for (int k = 0; k < K_; k++) {
                fo[k]     = fmaf(-e0, vp[k],     acc[k])     * i0 - vp[k];
                fo[4 + k] = fmaf(-e1, vp[4 + k], acc[4 + k]) * i1 - vp[4 + k];
                fo[8 + k] = fmaf(-e2, vp[8 + k], acc[8 + k]) * i2 - vp[8 + k];
            }
        }
    }
    __syncthreads();

    // ---- phase 1: h1 = relu(feat@W1.T + b1) -> fp16 A tile ----
    {
        const int n = tid;
        u64 w1p[FEAT_ / 2];
#pragma unroll
        for (int c = 0; c < FEAT_ / 2; c++)
            w1p[c] = *(const u64*)&W1[n * FEAT_ + 2 * c];
        const float bb = b1[n];
        __half* arow = (__half*)(smem + OFF_A) + n;
#pragma unroll 4
        for (int m = 0; m < MT_; m++) {
            u64 a = 0ULL;
#pragma unroll
            for (int c = 0; c < FEAT_ / 2; c++)
                a = fma2(*(const u64*)&sF[m * FEAT_ + 2 * c], w1p[c], a);
            const float2 f = u2f(a);
            arow[m * ASTRIDE] = __float2half_rn(fmaxf(f.x + f.y + bb, 0.f));
        }
    }
    __syncthreads();

    // ---- phase 2: 2-term HMMA GEMM, 8 K-panels of 32, double-buffered ----
    const int mwarp = wid >> 2, nwarp = wid & 3;   // 2(M) x 4(N)
    const int m0w = mwarp * 32, n0w = nwarp * 64;

    const uint32_t aBase = sb + OFF_A +
        (uint32_t)((m0w + (ln & 15)) * (ASTRIDE * 2) + (ln >> 4) * 16);
    const int rsel = (ln & 7) | (((ln >> 4) & 1) << 3);
    const int cpart = (ln >> 3) & 1;
    const int swz = (rsel >> 1) & 3;
    const uint32_t bRow = (uint32_t)((n0w + rsel) * 64);

    float acc[2][8][4];
#pragma unroll
    for (int i = 0; i < 2; i++)
#pragma unroll
        for (int j = 0; j < 8; j++)
#pragma unroll
            for (int c = 0; c < 4; c++) acc[i][j][c] = 0.f;

    for (int p = 0; p < NPAN_; p++) {
        if (p < NPAN_ - 1) {
            stageB(p + 1, (p + 1) & 1);
            asm volatile("cp.async.wait_group 1;" ::: "memory");
        } else {
            asm volatile("cp.async.wait_group 0;" ::: "memory");
        }
        __syncthreads();

        const uint32_t bBase = sb + OFF_B + (uint32_t)((p & 1) * BUFSZ) + bRow;

#pragma unroll
        for (int ks = 0; ks < 2; ks++) {
            uint32_t ah[2][4];
            const uint32_t ka = (uint32_t)(p * 64 + ks * 32);
#pragma unroll
            for (int i = 0; i < 2; i++)
                ldsm4(ah[i], aBase + ka + (uint32_t)(i * 16 * ASTRIDE * 2));
            const uint32_t bchunk = (uint32_t)(((ks * 2 + cpart) ^ swz) << 4);
#pragma unroll
            for (int jj = 0; jj < 4; jj++) {
                uint32_t bh[4], bl[4];
                const uint32_t bo = bchunk + (uint32_t)(jj * 16 * 64);
                ldsm4(bh, bBase + bo);
                ldsm4(bl, bBase + BPANEL + bo);
#pragma unroll
                for (int i = 0; i < 2; i++) {
                    mma16816(acc[i][2 * jj],     ah[i], bh[0], bh[1]);
                    mma16816(acc[i][2 * jj + 1], ah[i], bh[2], bh[3]);
                    mma16816(acc[i][2 * jj],     ah[i], bl[0], bl[1]);
                    mma16816(acc[i][2 * jj + 1], ah[i], bl[2], bl[3]);
                }
            }
        }
        __syncthreads();
    }

    // ---- epilogue: h2 = acc/64 + b2; relu; dot Wout; reduce ----
    float po[2][2] = {{0.f, 0.f}, {0.f, 0.f}};
#pragma unroll
    for (int i = 0; i < 2; i++)
#pragma unroll
        for (int j = 0; j < 8; j++) {
            const int nb = n0w + j * 8 + 2 * (ln & 3);
            const float2 bw0 = sBW[nb], bw1 = sBW[nb + 1];
            po[i][0] += fmaxf(fmaf(acc[i][j][0], INVWS, bw0.x), 0.f) * bw0.y
                      + fmaxf(fmaf(acc[i][j][1], INVWS, bw1.x), 0.f) * bw1.y;
            po[i][1] += fmaxf(fmaf(acc[i][j][2], INVWS, bw0.x), 0.f) * bw0.y
                      + fmaxf(fmaf(acc[i][j][3], INVWS, bw1.x), 0.f) * bw1.y;
        }
#pragma unroll
    for (int o = 1; o <= 2; o <<= 1)
#pragma unroll
        for (int i = 0; i < 2; i++) {
            po[i][0] += __shfl_xor_sync(0xffffffffu, po[i][0], o);
            po[i][1] += __shfl_xor_sync(0xffffffffu, po[i][1], o);
        }
    if ((ln & 3) == 0) {
        const int r = ln >> 2;
#pragma unroll
        for (int i = 0; i < 2; i++) {
            atomicAdd(&sred[m0w + i * 16 + r], po[i][0]);
            atomicAdd(&sred[m0w + i * 16 + 8 + r], po[i][1]);
        }
    }
    __syncthreads();
    if (tid < MT_) out[b * T_ + tok0 + tid] = sred[tid] + bout[0];
}

extern "C" void kernel_launch(void* const* d_in, const int* in_sizes, int n_in,
                              void* d_out, int out_size) {
    const float* state  = (const float*)d_in[0];
    const float* action = (const float*)d_in[1];
    const float* Wk     = (const float*)d_in[2];
    const float* Wq     = (const float*)d_in[3];
    const float* Wv     = (const float*)d_in[4];
    const float* W1     = (const float*)d_in[5];
    const float* b1     = (const float*)d_in[6];
    const float* W2     = (const float*)d_in[7];
    const float* b2     = (const float*)d_in[8];
    const float* Wout   = (const float*)d_in[9];
    const float* bout   = (const float*)d_in[10];
    float* out = (float*)d_out;

    const int smem = MT_ * ASTRIDE * 2 + 2 * (2 * HID_ * KP_ * 2) +
                     MT_ * FEAT_ * 4 + 2048 + 256;  // 107264
    cudaFuncSetAttribute(fused_kernel, cudaFuncAttributeMaxDynamicSharedMemorySize, smem);

    w2split_kernel<<<HID_ * HID_ / 256, 256>>>(W2);
    fused_kernel<<<2 * B_, 256, smem>>>(state, action, Wk, Wq, Wv,
                                        W1, b1, b2, Wout, bout, out);
}

// round 7
// speedup vs baseline: 1.7493x; 1.7493x over previous
#include <cuda_runtime.h>
#include <cuda_fp16.h>
#include <cstdint>

typedef unsigned long long u64;

namespace {
constexpr int B_ = 256, T_ = 128, SD_ = 8, AD_ = 2, H_ = 3, K_ = 4, HID_ = 256;
constexpr int QD_ = SD_ + AD_;    // 10
constexpr int HK_ = H_ * K_;      // 12
constexpr int FEAT_ = HK_ + QD_;  // 22
constexpr int MT_ = 128;          // tokens per CTA = one batch
constexpr int KP_ = 64;           // K panel
constexpr int ASTRIDE = 264;      // fp16 elems per A row (256 + 8 pad) -> 528B
constexpr int NTHR = 512;
constexpr float WSCALE = 64.f;
constexpr float INVWS = 1.f / 64.f;
constexpr int PSEG = 15 * MT_ + 4;  // padded partial segment (bank-decorrelated)
}

// W2*64 split into fp16 hi/lo
__device__ __half g_W2hi[HID_ * HID_];
__device__ __half g_W2lo[HID_ * HID_];

// ---------------- helpers ----------------
__device__ __forceinline__ u64 fma2(u64 a, u64 b, u64 c) {
    u64 d;
    asm("fma.rn.f32x2 %0, %1, %2, %3;" : "=l"(d) : "l"(a), "l"(b), "l"(c));
    return d;
}
__device__ __forceinline__ float2 u2f(u64 v) {
    float2 r;
    asm("mov.b64 {%0,%1}, %2;" : "=f"(r.x), "=f"(r.y) : "l"(v));
    return r;
}
__device__ __forceinline__ uint32_t smem_u32(const void* p) {
    uint32_t a;
    asm("{ .reg .u64 t; cvta.to.shared.u64 t, %1; cvt.u32.u64 %0, t; }" : "=r"(a) : "l"(p));
    return a;
}
__device__ __forceinline__ void ldsm4(uint32_t r[4], uint32_t addr) {
    asm volatile("ldmatrix.sync.aligned.m8n8.x4.shared.b16 {%0,%1,%2,%3}, [%4];"
                 : "=r"(r[0]), "=r"(r[1]), "=r"(r[2]), "=r"(r[3]) : "r"(addr));
}
__device__ __forceinline__ void mma16816(float c[4], const uint32_t a[4],
                                         uint32_t b0, uint32_t b1) {
    asm volatile(
        "mma.sync.aligned.m16n8k16.row.col.f32.f16.f16.f32 "
        "{%0,%1,%2,%3}, {%4,%5,%6,%7}, {%8,%9}, {%0,%1,%2,%3};"
        : "+f"(c[0]), "+f"(c[1]), "+f"(c[2]), "+f"(c[3])
        : "r"(a[0]), "r"(a[1]), "r"(a[2]), "r"(a[3]), "r"(b0), "r"(b1));
}
__device__ __forceinline__ void cp_async16(uint32_t dst, const void* src) {
    asm volatile("cp.async.ca.shared.global [%0], [%1], 16;" :: "r"(dst), "l"(src) : "memory");
}

// ---------------------------------------------------------------------------
// Kernel W: W2*64 -> fp16 hi/lo residual pair
// ---------------------------------------------------------------------------
__global__ __launch_bounds__(256) void w2split_kernel(const float* __restrict__ W2) {
    const int i = blockIdx.x * 256 + threadIdx.x;
    const float w = W2[i] * WSCALE;
    const __half hi = __float2half_rn(w);
    g_W2hi[i] = hi;
    g_W2lo[i] = __float2half_rn(w - __half2float(hi));
}

// ---------------------------------------------------------------------------
// Fused kernel: one CTA = one batch (128 tokens), 512 threads, 16 warps.
//   phase 0: attention; jj-loop split 4-way (interleaved); both B buffers
//            prefetched via cp.async before attention begins.
//   phase 1: h1 = relu(feat@W1.T+b1); 2 threads/column, 64 m each.
//   phase 2: HMMA D = A@(64*W2)hi^T + A@(64*W2)lo^T, 4 K-panels of 64,
//            16 warps = 4(M)x4(N), warp tile 32x64 (acc = 64 regs).
//   epilogue: h2 = D/64 + b2; relu; dot Wout; reduce; +bout.
// ---------------------------------------------------------------------------
__global__ __launch_bounds__(NTHR, 1) void fused_kernel(
    const float* __restrict__ state, const float* __restrict__ action,
    const float* __restrict__ Wk, const float* __restrict__ Wq,
    const float* __restrict__ Wv,
    const float* __restrict__ W1, const float* __restrict__ b1,
    const float* __restrict__ b2, const float* __restrict__ Wout,
    const float* __restrict__ bout, float* __restrict__ out)
{
    extern __shared__ char smem[];
    constexpr int ABYTES = MT_ * ASTRIDE * 2;          // 67584
    constexpr int OFF_A  = 0;
    constexpr int OFF_B  = ABYTES;
    constexpr int BPANEL = HID_ * KP_ * 2;             // 32768 (one hi or lo panel)
    constexpr int BUFSZ  = 2 * BPANEL;                 // 65536
    constexpr int OFF_F  = OFF_B + 2 * BUFSZ;          // feat [128][22] f32 = 11264
    constexpr int OFF_BW = OFF_F + MT_ * FEAT_ * 4;    // float2 x 256 = 2048
    constexpr int OFF_RED = OFF_BW + 2048;             // float x 128
    // aliases inside A region (dead once phase 1 starts)
    constexpr int OFF_SK = 0;                          // float [128][12] = 6144
    constexpr int OFF_SV = 6144;
    constexpr int OFF_PART = 12288;                    // 3 segments of PSEG floats

    const uint32_t sb = smem_u32(smem);
    const int tid = threadIdx.x, wid = tid >> 5, ln = tid & 31;
    const int b = blockIdx.x;

    float* sF = (float*)(smem + OFF_F);
    float2* sBW = (float2*)(smem + OFF_BW);
    float* sred = (float*)(smem + OFF_RED);
    float (*sK)[HK_] = (float(*)[HK_])(smem + OFF_SK);
    float (*sV)[HK_] = (float(*)[HK_])(smem + OFF_SV);
    float* sPART = (float*)(smem + OFF_PART);

    // ---- stage B panel p into buffer buf (128B rows, XOR-16B swizzle) ----
    auto stageB = [&](int p, int buf) {
        for (int it = tid; it < 2048; it += NTHR) {
            const int row = it >> 3, c = it & 7;
            const uint32_t dst = sb + OFF_B + (uint32_t)(buf * BUFSZ + row * 128 +
                                                         ((c ^ (row & 7)) << 4));
            cp_async16(dst, g_W2hi + row * HID_ + p * KP_ + c * 8);
            cp_async16(dst + BPANEL, g_W2lo + row * HID_ + p * KP_ + c * 8);
        }
        asm volatile("cp.async.commit_group;" ::: "memory");
    };
    stageB(0, 0);   // both buffers prefetched before attention
    stageB(1, 1);

    if (tid < 256) sBW[tid] = make_float2(b2[tid], Wout[tid]);
    if (tid < MT_) sred[tid] = 0.f;

    // ---- phase 0: attention ----
    const int t_loc = tid >> 2, tsub = tid & 3;
    if (tid < T_) {
        const float4 s4 = *(const float4*)(state + (size_t)(b * T_ + tid) * SD_);
#pragma unroll
        for (int i = 0; i < HK_; i++) {
            sK[tid][i] = s4.x * Wk[i * 4] + s4.y * Wk[i * 4 + 1] +
                         s4.z * Wk[i * 4 + 2] + s4.w * Wk[i * 4 + 3];
            sV[tid][i] = s4.x * Wv[i * 4] + s4.y * Wv[i * 4 + 1] +
                         s4.z * Wv[i * 4 + 2] + s4.w * Wv[i * 4 + 3];
        }
    }
    float q[HK_];
    {
        const int tg = b * T_ + t_loc;
        const float* st = state + (size_t)tg * SD_;
        const float* ac = action + (size_t)tg * AD_;
        float qs[QD_];
#pragma unroll
        for (int c = 0; c < SD_; c++) qs[c] = st[c];
        qs[SD_] = ac[0];
        qs[SD_ + 1] = ac[1];
#pragma unroll
        for (int i = 0; i < HK_; i++) {
            float a = 0.f;
#pragma unroll
            for (int c = 0; c < QD_; c++) a = fmaf(qs[c], Wq[i * QD_ + c], a);
            q[i] = a;
        }
        if (tsub == 0) {
            float* fo = sF + t_loc * FEAT_;
#pragma unroll
            for (int c = 0; c < QD_; c++) fo[HK_ + c] = qs[c];
        }
    }
    __syncthreads();

    {
        float sum0 = 0.f, sum1 = 0.f, sum2 = 0.f;
        float acc[HK_];
#pragma unroll
        for (int i = 0; i < HK_; i++) acc[i] = 0.f;
#pragma unroll 4
        for (int jx = 0; jx < 32; jx++) {
            const int jj = tsub + 4 * jx;  // interleaved: distinct banks per warp
            const float4 k0 = *(const float4*)&sK[jj][0];
            const float4 k1 = *(const float4*)&sK[jj][4];
            const float4 k2 = *(const float4*)&sK[jj][8];
            float s0 = q[0]*k0.x + q[1]*k0.y + q[2]*k0.z + q[3]*k0.w;
            float s1 = q[4]*k1.x + q[5]*k1.y + q[6]*k1.z + q[7]*k1.w;
            float s2 = q[8]*k2.x + q[9]*k2.y + q[10]*k2.z + q[11]*k2.w;
            const float e0 = __expf(0.5f * s0);
            const float e1 = __expf(0.5f * s1);
            const float e2 = __expf(0.5f * s2);
            sum0 += e0; sum1 += e1; sum2 += e2;
            const float4 v0 = *(const float4*)&sV[jj][0];
            const float4 v1 = *(const float4*)&sV[jj][4];
            const float4 v2 = *(const float4*)&sV[jj][8];
            acc[0]  = fmaf(e0, v0.x, acc[0]);  acc[1]  = fmaf(e0, v0.y, acc[1]);
            acc[2]  = fmaf(e0, v0.z, acc[2]);  acc[3]  = fmaf(e0, v0.w, acc[3]);
            acc[4]  = fmaf(e1, v1.x, acc[4]);  acc[5]  = fmaf(e1, v1.y, acc[5]);
            acc[6]  = fmaf(e1, v1.z, acc[6]);  acc[7]  = fmaf(e1, v1.w, acc[7]);
            acc[8]  = fmaf(e2, v2.x, acc[8]);  acc[9]  = fmaf(e2, v2.y, acc[9]);
            acc[10] = fmaf(e2, v2.z, acc[10]); acc[11] = fmaf(e2, v2.w, acc[11]);
        }
        if (tsub) {
            float* pp = sPART + (tsub - 1) * PSEG + t_loc;
            pp[0] = sum0; pp[MT_] = sum1; pp[2 * MT_] = sum2;
#pragma unroll
            for (int i = 0; i < HK_; i++) pp[(3 + i) * MT_] = acc[i];
        }
        __syncthreads();
        if (tsub == 0) {
#pragma unroll
            for (int s = 0; s < 3; s++) {
                const float* pp = sPART + s * PSEG + t_loc;
                sum0 += pp[0]; sum1 += pp[MT_]; sum2 += pp[2 * MT_];
#pragma unroll
                for (int i = 0; i < HK_; i++) acc[i] += pp[(3 + i) * MT_];
            }
            // subtract self (jj == t_loc)
            const int ts = t_loc;
            const float4 k0 = *(const float4*)&sK[ts][0];
            const float4 k1 = *(const float4*)&sK[ts][4];
            const float4 k2 = *(const float4*)&sK[ts][8];
            float s0 = q[0]*k0.x + q[1]*k0.y + q[2]*k0.z + q[3]*k0.w;
            float s1 = q[4]*k1.x + q[5]*k1.y + q[6]*k1.z + q[7]*k1.w;
            float s2 = q[8]*k2.x + q[9]*k2.y + q[10]*k2.z + q[11]*k2.w;
            const float e0 = __expf(0.5f * s0);
            const float e1 = __expf(0.5f * s1);
            const float e2 = __expf(0.5f * s2);
            sum0 -= e0; sum1 -= e1; sum2 -= e2;
            const float4 v0 = *(const float4*)&sV[ts][0];
            const float4 v1 = *(const float4*)&sV[ts][4];
            const float4 v2 = *(const float4*)&sV[ts][8];
            const float vp[HK_] = {v0.x, v0.y, v0.z, v0.w, v1.x, v1.y, v1.z, v1.w,
                                   v2.x, v2.y, v2.z, v2.w};
            const float i0 = 1.f / sum0, i1 = 1.f / sum1, i2 = 1.f / sum2;
            float* fo = sF + t_loc * FEAT_;
#pragma unroll
            for (int k = 0; k < K_; k++) {
                fo[k]     = fmaf(-e0, vp[k],     acc[k])     * i0 - vp[k];
                fo[4 + k] = fmaf(-e1, vp[4 + k], acc[4 + k]) * i1 - vp[4 + k];
                fo[8 + k] = fmaf(-e2, vp[8 + k], acc[8 + k]) * i2 - vp[8 + k];
            }
        }
    }
    __syncthreads();

    // ---- phase 1: h1 = relu(feat@W1.T + b1) -> fp16 A tile; 2 thr/column ----
    {
        const int n = tid & 255, mh = tid >> 8;
        u64 w1p[FEAT_ / 2];
#pragma unroll
        for (int c = 0; c < FEAT_ / 2; c++)
            w1p[c] = *(const u64*)&W1[n * FEAT_ + 2 * c];
        const float bb = b1[n];
        __half* arow = (__half*)(smem + OFF_A) + n;
        const int m0 = mh * 64;
#pragma unroll 4
        for (int mm = 0; mm < 64; mm++) {
            const int m = m0 + mm;
            u64 a = 0ULL;
#pragma unroll
            for (int c = 0; c < FEAT_ / 2; c++)
                a = fma2(*(const u64*)&sF[m * FEAT_ + 2 * c], w1p[c], a);
            const float2 f = u2f(a);
            arow[m * ASTRIDE] = __float2half_rn(fmaxf(f.x + f.y + bb, 0.f));
        }
    }
    __syncthreads();

    // ---- phase 2: 2-term HMMA GEMM, 4 K-panels, 16 warps = 4(M) x 4(N) ----
    const int mwarp = wid >> 2, nwarp = wid & 3;
    const int m0w = mwarp * 32, n0w = nwarp * 64;

    const uint32_t aBase = sb + OFF_A +
        (uint32_t)((m0w + (ln & 15)) * (ASTRIDE * 2) + (ln >> 4) * 16);
    const int rsel = (ln & 7) | (((ln >> 4) & 1) << 3);
    const int swz = ln & 7;
    const int cpart = (ln >> 3) & 1;
    const uint32_t bRow = (uint32_t)((n0w + rsel) * 128);

    float acc[2][8][4];
#pragma unroll
    for (int i = 0; i < 2; i++)
#pragma unroll
        for (int j = 0; j < 8; j++)
#pragma unroll
            for (int c = 0; c < 4; c++) acc[i][j][c] = 0.f;

    for (int p = 0; p < 4; p++) {
        if (p < 3) asm volatile("cp.async.wait_group 1;" ::: "memory");
        else       asm volatile("cp.async.wait_group 0;" ::: "memory");
        __syncthreads();

        const uint32_t bBase = sb + OFF_B + (uint32_t)((p & 1) * BUFSZ) + bRow;

#pragma unroll
        for (int ks = 0; ks < 4; ks++) {
            uint32_t ah[2][4];
            const uint32_t ka = (uint32_t)(p * 128 + ks * 32);
#pragma unroll
            for (int i = 0; i < 2; i++)
                ldsm4(ah[i], aBase + ka + (uint32_t)(i * 16 * ASTRIDE * 2));
            const uint32_t bchunk = (uint32_t)(((ks * 2 + cpart) ^ swz) << 4);
#pragma unroll
            for (int jj = 0; jj < 4; jj++) {
                uint32_t bh[4], bl[4];
                const uint32_t bo = bchunk + (uint32_t)(jj * 16 * 128);
                ldsm4(bh, bBase + bo);
                ldsm4(bl, bBase + BPANEL + bo);
#pragma unroll
                for (int i = 0; i < 2; i++) {
                    mma16816(acc[i][2 * jj],     ah[i], bh[0], bh[1]);
                    mma16816(acc[i][2 * jj + 1], ah[i], bh[2], bh[3]);
                    mma16816(acc[i][2 * jj],     ah[i], bl[0], bl[1]);
                    mma16816(acc[i][2 * jj + 1], ah[i], bl[2], bl[3]);
                }
            }
        }
        __syncthreads();
        if (p < 2) stageB(p + 2, p & 1);  // overlap staging with next panel's MMAs
    }

    // ---- epilogue: h2 = acc/64 + b2; relu; dot Wout; reduce ----
    float po[2][2] = {{0.f, 0.f}, {0.f, 0.f}};
#pragma unroll
    for (int i = 0; i < 2; i++)
#pragma unroll
        for (int j = 0; j < 8; j++) {
            const int nb = n0w + j * 8 + 2 * (ln & 3);
            const float2 bw0 = sBW[nb], bw1 = sBW[nb + 1];
            po[i][0] += fmaxf(fmaf(acc[i][j][0], INVWS, bw0.x), 0.f) * bw0.y
                      + fmaxf(fmaf(acc[i][j][1], INVWS, bw1.x), 0.f) * bw1.y;
            po[i][1] += fmaxf(fmaf(acc[i][j][2], INVWS, bw0.x), 0.f) * bw0.y
                      + fmaxf(fmaf(acc[i][j][3], INVWS, bw1.x), 0.f) * bw1.y;
        }
#pragma unroll
    for (int o = 1; o <= 2; o <<= 1)
#pragma unroll
        for (int i = 0; i < 2; i++) {
            po[i][0] += __shfl_xor_sync(0xffffffffu, po[i][0], o);
            po[i][1] += __shfl_xor_sync(0xffffffffu, po[i][1], o);
        }
    if ((ln & 3) == 0) {
        const int r = ln >> 2;
#pragma unroll
        for (int i = 0; i < 2; i++) {
            atomicAdd(&sred[m0w + i * 16 + r], po[i][0]);
            atomicAdd(&sred[m0w + i * 16 + 8 + r], po[i][1]);
        }
    }
    __syncthreads();
    if (tid < MT_) out[b * T_ + tid] = sred[tid] + bout[0];
}

extern "C" void kernel_launch(void* const* d_in, const int* in_sizes, int n_in,
                              void* d_out, int out_size) {
    const float* state  = (const float*)d_in[0];
    const float* action = (const float*)d_in[1];
    const float* Wk     = (const float*)d_in[2];
    const float* Wq     = (const float*)d_in[3];
    const float* Wv     = (const float*)d_in[4];
    const float* W1     = (const float*)d_in[5];
    const float* b1     = (const float*)d_in[6];
    const float* W2     = (const float*)d_in[7];
    const float* b2     = (const float*)d_in[8];
    const float* Wout   = (const float*)d_in[9];
    const float* bout   = (const float*)d_in[10];
    float* out = (float*)d_out;

    const int smem = MT_ * ASTRIDE * 2 + 2 * (2 * HID_ * KP_ * 2) +
                     MT_ * FEAT_ * 4 + 2048 + 512 + 256;  // ~213.5 KB
    cudaFuncSetAttribute(fused_kernel, cudaFuncAttributeMaxDynamicSharedMemorySize, smem);

    w2split_kernel<<<HID_ * HID_ / 256, 256>>>(W2);
    fused_kernel<<<B_, NTHR, smem>>>(state, action, Wk, Wq, Wv,
                                     W1, b1, b2, Wout, bout, out);
}

// round 8
// speedup vs baseline: 2.1609x; 1.2353x over previous
#include <cuda_runtime.h>
#include <cuda_fp16.h>
#include <cstdint>

typedef unsigned long long u64;

namespace {
constexpr int B_ = 256, T_ = 128, SD_ = 8, AD_ = 2, H_ = 3, K_ = 4, HID_ = 256;
constexpr int QD_ = SD_ + AD_;    // 10
constexpr int HK_ = H_ * K_;      // 12
constexpr int FEAT_ = HK_ + QD_;  // 22
constexpr int MT_ = 128;          // tokens per CTA = one batch
constexpr int KP_ = 64;           // main-GEMM K panel
constexpr int ASTRIDE = 264;      // fp16 elems per A row (256 + 8 pad) -> 528B
constexpr float WSCALE = 64.f;
constexpr float INVWS = 1.f / 64.f;
}

// pre-split weights (×64)
__device__ __half g_W2hi[HID_ * HID_];
__device__ __half g_W2lo[HID_ * HID_];
__device__ __half g_W1hi[HID_ * 32];   // [256][32], cols 22..31 zero
__device__ __half g_W1lo[HID_ * 32];

// ---------------- helpers ----------------
__device__ __forceinline__ uint32_t smem_u32(const void* p) {
    uint32_t a;
    asm("{ .reg .u64 t; cvta.to.shared.u64 t, %1; cvt.u32.u64 %0, t; }" : "=r"(a) : "l"(p));
    return a;
}
__device__ __forceinline__ void ldsm4(uint32_t r[4], uint32_t addr) {
    asm volatile("ldmatrix.sync.aligned.m8n8.x4.shared.b16 {%0,%1,%2,%3}, [%4];"
                 : "=r"(r[0]), "=r"(r[1]), "=r"(r[2]), "=r"(r[3]) : "r"(addr));
}
__device__ __forceinline__ void mma16816(float c[4], const uint32_t a[4],
                                         uint32_t b0, uint32_t b1) {
    asm volatile(
        "mma.sync.aligned.m16n8k16.row.col.f32.f16.f16.f32 "
        "{%0,%1,%2,%3}, {%4,%5,%6,%7}, {%8,%9}, {%0,%1,%2,%3};"
        : "+f"(c[0]), "+f"(c[1]), "+f"(c[2]), "+f"(c[3])
        : "r"(a[0]), "r"(a[1]), "r"(a[2]), "r"(a[3]), "r"(b0), "r"(b1));
}
__device__ __forceinline__ void cp_async16(uint32_t dst, const void* src) {
    asm volatile("cp.async.ca.shared.global [%0], [%1], 16;" :: "r"(dst), "l"(src) : "memory");
}
__device__ __forceinline__ uint32_t pack_half2(float lo, float hi) {
    __half2 h = __floats2half2_rn(lo, hi);
    return *(uint32_t*)&h;
}

// ---------------------------------------------------------------------------
// Prep: W2*64 -> fp16 hi/lo ; W1*64 -> fp16 hi/lo (K padded 22 -> 32)
// ---------------------------------------------------------------------------
__global__ __launch_bounds__(256) void w2split_kernel(const float* __restrict__ W2) {
    const int i = blockIdx.x * 256 + threadIdx.x;
    const float w = W2[i] * WSCALE;
    const __half hi = __float2half_rn(w);
    g_W2hi[i] = hi;
    g_W2lo[i] = __float2half_rn(w - __half2float(hi));
}
__global__ __launch_bounds__(256) void w1split_kernel(const float* __restrict__ W1) {
    const int i = blockIdx.x * 256 + threadIdx.x;   // 8192 total
    const int n = i >> 5, k = i & 31;
    const float w = (k < FEAT_) ? W1[n * FEAT_ + k] * WSCALE : 0.f;
    const __half hi = __float2half_rn(w);
    g_W1hi[i] = hi;
    g_W1lo[i] = __float2half_rn(w - __half2float(hi));
}

// ---------------------------------------------------------------------------
// Fused kernel: one CTA = one batch (128 tokens), 256 threads, 8 warps.
//   phase 0: attention (2-way jj split), feat written as fp16 hi/lo tile.
//   phase 1: h1 via HMMA (3-term: Fhi*Whi + Fhi*Wlo + Flo*Whi, K=32),
//            relu(D/64+b1) -> fp16 -> main A tile.
//   phase 2: main HMMA D = A@(64*W2)hi^T + A@(64*W2)lo^T, 4 K-panels of 64,
//            double-buffered cp.async.
//   epilogue: h2 = D/64 + b2; relu; dot Wout; reduce; +bout.
// ---------------------------------------------------------------------------
__global__ __launch_bounds__(256) void fused_kernel(
    const float* __restrict__ state, const float* __restrict__ action,
    const float* __restrict__ Wk, const float* __restrict__ Wq,
    const float* __restrict__ Wv,
    const float* __restrict__ b1, const float* __restrict__ b2,
    const float* __restrict__ Wout, const float* __restrict__ bout,
    float* __restrict__ out)
{
    extern __shared__ char smem[];
    constexpr int ABYTES = MT_ * ASTRIDE * 2;          // 67584
    constexpr int OFF_A  = 0;
    constexpr int OFF_B  = ABYTES;
    constexpr int BPANEL = HID_ * KP_ * 2;             // 32768
    constexpr int BUFSZ  = 2 * BPANEL;                 // 65536
    // buf1 region aliases (dead until main panel 1 staged):
    constexpr int OFF_W1T = OFF_B + BUFSZ;             // W1 hi 16384 | lo 16384
    constexpr int OFF_FH  = OFF_W1T + 32768;           // feat hi [128][64B] = 8192
    constexpr int OFF_FL  = OFF_FH + 8192;             // feat lo 8192
    constexpr int OFF_BW  = OFF_B + 2 * BUFSZ;         // float2 x 256 = 2048
    constexpr int OFF_B1  = OFF_BW + 2048;             // float x 256
    constexpr int OFF_RED = OFF_B1 + 1024;             // float x 128
    // aliases inside A region (dead until phase 1 writes A)
    constexpr int OFF_SK = 0, OFF_SV = 6144, OFF_PART = 12288;

    const uint32_t sb = smem_u32(smem);
    const int tid = threadIdx.x, wid = tid >> 5, ln = tid & 31;
    const int b = blockIdx.x;

    float2* sBW = (float2*)(smem + OFF_BW);
    float* sB1 = (float*)(smem + OFF_B1);
    float* sred = (float*)(smem + OFF_RED);
    float (*sK)[HK_] = (float(*)[HK_])(smem + OFF_SK);
    float (*sV)[HK_] = (float(*)[HK_])(smem + OFF_SV);
    float (*sPA)[MT_] = (float(*)[MT_])(smem + OFF_PART);

    // ---- stage main B panel p into buffer buf (128B rows, XOR-16B swizzle) ----
    auto stageB = [&](int p, int buf) {
        for (int it = tid; it < 2048; it += 256) {
            const int row = it >> 3, c = it & 7;
            const uint32_t dst = sb + OFF_B + (uint32_t)(buf * BUFSZ + row * 128 +
                                                         ((c ^ (row & 7)) << 4));
            cp_async16(dst, g_W2hi + row * HID_ + p * KP_ + c * 8);
            cp_async16(dst + BPANEL, g_W2lo + row * HID_ + p * KP_ + c * 8);
        }
        asm volatile("cp.async.commit_group;" ::: "memory");
    };
    stageB(0, 0);
    // stage W1 tiles (64B rows, chunk c ^= (row>>1)&3)
    for (int it = tid; it < 2048; it += 256) {
        const int hl = it >> 10, idx = it & 1023, row = idx >> 2, c = idx & 3;
        const uint32_t dst = sb + OFF_W1T + (uint32_t)(hl * 16384 + row * 64 +
                                                       ((c ^ ((row >> 1) & 3)) << 4));
        cp_async16(dst, (hl ? g_W1lo : g_W1hi) + row * 32 + c * 8);
    }
    asm volatile("cp.async.commit_group;" ::: "memory");

    // zero feat tiles (pad cols 22..31 stay 0)
    {
        float4* z = (float4*)(smem + OFF_FH);
#pragma unroll
        for (int i = 0; i < 4; i++) z[tid + i * 256] = make_float4(0.f, 0.f, 0.f, 0.f);
    }
    sBW[tid] = make_float2(b2[tid], Wout[tid]);
    sB1[tid] = b1[tid];
    if (tid < MT_) sred[tid] = 0.f;

    // ---- phase 0: attention (round-5 structure) ----
    const int half = tid >> 7, t = tid & 127;
    float qs[QD_], q[HK_], kp[HK_], vp[HK_];
    {
        const float* st = state + (size_t)(b * T_ + t) * SD_;
        const float* ac = action + (size_t)(b * T_ + t) * AD_;
#pragma unroll
        for (int c = 0; c < SD_; c++) qs[c] = st[c];
        qs[SD_] = ac[0];
        qs[SD_ + 1] = ac[1];
#pragma unroll
        for (int i = 0; i < HK_; i++) {
            float a = 0.f;
#pragma unroll
            for (int c = 0; c < QD_; c++) a = fmaf(qs[c], Wq[i * QD_ + c], a);
            q[i] = a;
        }
#pragma unroll
        for (int i = 0; i < HK_; i++) {
            float ak = 0.f, av = 0.f;
#pragma unroll
            for (int c = 0; c < K_; c++) {
                ak = fmaf(qs[c], Wk[i * K_ + c], ak);
                av = fmaf(qs[c], Wv[i * K_ + c], av);
            }
            kp[i] = ak; vp[i] = av;
        }
        if (half == 0) {
#pragma unroll
            for (int i = 0; i < HK_; i++) { sK[t][i] = kp[i]; sV[t][i] = vp[i]; }
        }
    }
    __syncthreads();

    {
        float sum0 = 0.f, sum1 = 0.f, sum2 = 0.f;
        float acc[HK_];
#pragma unroll
        for (int i = 0; i < HK_; i++) acc[i] = 0.f;
        const int j0 = half * 64;
#pragma unroll 4
        for (int jx = 0; jx < 64; jx++) {
            const int jj = j0 + jx;
            const float4 k0 = *(const float4*)&sK[jj][0];
            const float4 k1 = *(const float4*)&sK[jj][4];
            const float4 k2 = *(const float4*)&sK[jj][8];
            float s0 = q[0]*k0.x + q[1]*k0.y + q[2]*k0.z + q[3]*k0.w;
            float s1 = q[4]*k1.x + q[5]*k1.y + q[6]*k1.z + q[7]*k1.w;
            float s2 = q[8]*k2.x + q[9]*k2.y + q[10]*k2.z + q[11]*k2.w;
            const float e0 = __expf(0.5f * s0);
            const float e1 = __expf(0.5f * s1);
            const float e2 = __expf(0.5f * s2);
            sum0 += e0; sum1 += e1; sum2 += e2;
            const float4 v0 = *(const float4*)&sV[jj][0];
            const float4 v1 = *(const float4*)&sV[jj][4];
            const float4 v2 = *(const float4*)&sV[jj][8];
            acc[0]  = fmaf(e0, v0.x, acc[0]);  acc[1]  = fmaf(e0, v0.y, acc[1]);
            acc[2]  = fmaf(e0, v0.z, acc[2]);  acc[3]  = fmaf(e0, v0.w, acc[3]);
            acc[4]  = fmaf(e1, v1.x, acc[4]);  acc[5]  = fmaf(e1, v1.y, acc[5]);
            acc[6]  = fmaf(e1, v1.z, acc[6]);  acc[7]  = fmaf(e1, v1.w, acc[7]);
            acc[8]  = fmaf(e2, v2.x, acc[8]);  acc[9]  = fmaf(e2, v2.y, acc[9]);
            acc[10] = fmaf(e2, v2.z, acc[10]); acc[11] = fmaf(e2, v2.w, acc[11]);
        }
        if (half == 1) {
            sPA[0][t] = sum0; sPA[1][t] = sum1; sPA[2][t] = sum2;
#pragma unroll
            for (int i = 0; i < HK_; i++) sPA[3 + i][t] = acc[i];
        }
        __syncthreads();
        if (half == 0) {
            sum0 += sPA[0][t]; sum1 += sPA[1][t]; sum2 += sPA[2][t];
#pragma unroll
            for (int i = 0; i < HK_; i++) acc[i] += sPA[3 + i][t];
            float s0 = q[0]*kp[0] + q[1]*kp[1] + q[2]*kp[2] + q[3]*kp[3];
            float s1 = q[4]*kp[4] + q[5]*kp[5] + q[6]*kp[6] + q[7]*kp[7];
            float s2 = q[8]*kp[8] + q[9]*kp[9] + q[10]*kp[10] + q[11]*kp[11];
            const float e0 = __expf(0.5f * s0);
            const float e1 = __expf(0.5f * s1);
            const float e2 = __expf(0.5f * s2);
            sum0 -= e0; sum1 -= e1; sum2 -= e2;
            const float i0 = 1.f / sum0, i1 = 1.f / sum1, i2 = 1.f / sum2;
            float f[FEAT_];
#pragma unroll
            for (int k = 0; k < K_; k++) {
                f[k]     = fmaf(-e0, vp[k],     acc[k])     * i0 - vp[k];
                f[4 + k] = fmaf(-e1, vp[4 + k], acc[4 + k]) * i1 - vp[4 + k];
                f[8 + k] = fmaf(-e2, vp[8 + k], acc[8 + k]) * i2 - vp[8 + k];
            }
#pragma unroll
            for (int c = 0; c < QD_; c++) f[HK_ + c] = qs[c];
            // write feat as fp16 hi/lo into swizzled [128][32] tiles
#pragma unroll
            for (int c = 0; c < FEAT_; c++) {
                const float v = f[c];
                const __half hi = __float2half_rn(v);
                const float lo = v - __half2float(hi);
                const uint32_t ad = (uint32_t)(t * 64 + (((c >> 3) ^ ((t >> 1) & 3)) << 4) +
                                               (c & 7) * 2);
                *(__half*)(smem + OFF_FH + ad) = hi;
                *(__half*)(smem + OFF_FL + ad) = __float2half_rn(lo);
            }
        }
    }
    asm volatile("cp.async.wait_group 0;" ::: "memory");
    __syncthreads();

    // ---- warp tiling (shared by W1-GEMM and main GEMM): 4(M) x 2(N) ----
    const int mwarp = wid >> 1, nwarp = wid & 1;
    const int m0w = mwarp * 32, n0w = nwarp * 128;
    const int rsel = (ln & 7) | (((ln >> 4) & 1) << 3);
    const int cpart = (ln >> 3) & 1;

    float acc[2][16][4];
#pragma unroll
    for (int i = 0; i < 2; i++)
#pragma unroll
        for (int j = 0; j < 16; j++)
#pragma unroll
            for (int c = 0; c < 4; c++) acc[i][j][c] = 0.f;

    // ---- phase 1: W1 HMMA (3-term, K=32) ----
    {
        const int aRow = m0w + (ln & 15);
        const int aSw = (aRow >> 1) & 3;
        const int aCS = ln >> 4;
        const int bSw = (rsel >> 1) & 3;
#pragma unroll
        for (int ks = 0; ks < 2; ks++) {
            uint32_t ah[2][4], al[2][4];
#pragma unroll
            for (int i = 0; i < 2; i++) {
                const uint32_t ad = sb + OFF_FH + (uint32_t)((aRow + i * 16) * 64 +
                                    (((ks * 2 + aCS) ^ aSw) << 4));
                ldsm4(ah[i], ad);
                ldsm4(al[i], ad + 8192);  // lo tile
            }
#pragma unroll
            for (int j = 0; j < 8; j++) {
                const uint32_t bd = sb + OFF_W1T + (uint32_t)((n0w + j * 16 + rsel) * 64 +
                                    (((ks * 2 + cpart) ^ bSw) << 4));
                uint32_t bh[4], bl[4];
                ldsm4(bh, bd);
                ldsm4(bl, bd + 16384);
#pragma unroll
                for (int i = 0; i < 2; i++) {
                    mma16816(acc[i][2 * j],     ah[i], bh[0], bh[1]);
                    mma16816(acc[i][2 * j + 1], ah[i], bh[2], bh[3]);
                    mma16816(acc[i][2 * j],     ah[i], bl[0], bl[1]);
                    mma16816(acc[i][2 * j + 1], ah[i], bl[2], bl[3]);
                    mma16816(acc[i][2 * j],     al[i], bh[0], bh[1]);
                    mma16816(acc[i][2 * j + 1], al[i], bh[2], bh[3]);
                }
            }
        }
        // h1 = relu(D/64 + b1) -> fp16 -> main A tile (row-major, padded stride)
#pragma unroll
        for (int i = 0; i < 2; i++) {
            const int r0 = m0w + i * 16 + (ln >> 2);
#pragma unroll
            for (int j = 0; j < 16; j++) {
                const int n = n0w + j * 8 + 2 * (ln & 3);
                const float h0 = fmaxf(fmaf(acc[i][j][0], INVWS, sB1[n]), 0.f);
                const float h1v = fmaxf(fmaf(acc[i][j][1], INVWS, sB1[n + 1]), 0.f);
                const float h2 = fmaxf(fmaf(acc[i][j][2], INVWS, sB1[n]), 0.f);
                const float h3 = fmaxf(fmaf(acc[i][j][3], INVWS, sB1[n + 1]), 0.f);
                *(uint32_t*)(smem + OFF_A + r0 * (ASTRIDE * 2) + n * 2) = pack_half2(h0, h1v);
                *(uint32_t*)(smem + OFF_A + (r0 + 8) * (ASTRIDE * 2) + n * 2) = pack_half2(h2, h3);
            }
        }
    }
    __syncthreads();

    // ---- phase 2: main 2-term HMMA GEMM, 4 K-panels, double-buffered ----
#pragma unroll
    for (int i = 0; i < 2; i++)
#pragma unroll
        for (int j = 0; j < 16; j++)
#pragma unroll
            for (int c = 0; c < 4; c++) acc[i][j][c] = 0.f;

    const uint32_t aBase = sb + OFF_A +
        (uint32_t)((m0w + (ln & 15)) * (ASTRIDE * 2) + (ln >> 4) * 16);
    const int swz = ln & 7;
    const uint32_t bRow = (uint32_t)((n0w + rsel) * 128);

    for (int p = 0; p < 4; p++) {
        if (p < 3) {
            stageB(p + 1, (p + 1) & 1);
            asm volatile("cp.async.wait_group 1;" ::: "memory");
        } else {
            asm volatile("cp.async.wait_group 0;" ::: "memory");
        }
        __syncthreads();

        const uint32_t bBase = sb + OFF_B + (uint32_t)((p & 1) * BUFSZ) + bRow;

#pragma unroll
        for (int ks = 0; ks < 4; ks++) {
            uint32_t ah[2][4];
            const uint32_t ka = (uint32_t)(p * 128 + ks * 32);
#pragma unroll
            for (int i = 0; i < 2; i++)
                ldsm4(ah[i], aBase + ka + (uint32_t)(i * 16 * ASTRIDE * 2));
            const uint32_t bchunk = (uint32_t)(((ks * 2 + cpart) ^ swz) << 4);
#pragma unroll
            for (int jj = 0; jj < 8; jj++) {
                uint32_t bh[4], bl[4];
                const uint32_t bo = bchunk + (uint32_t)(jj * 16 * 128);
                ldsm4(bh, bBase + bo);
                ldsm4(bl, bBase + BPANEL + bo);
#pragma unroll
                for (int i = 0; i < 2; i++) {
                    mma16816(acc[i][2 * jj],     ah[i], bh[0], bh[1]);
                    mma16816(acc[i][2 * jj + 1], ah[i], bh[2], bh[3]);
                    mma16816(acc[i][2 * jj],     ah[i], bl[0], bl[1]);
                    mma16816(acc[i][2 * jj + 1], ah[i], bl[2], bl[3]);
                }
            }
        }
        __syncthreads();
    }

    // ---- epilogue: h2 = acc/64 + b2; relu; dot Wout; reduce ----
    float po[2][2] = {{0.f, 0.f}, {0.f, 0.f}};
#pragma unroll
    for (int i = 0; i < 2; i++)
#pragma unroll
        for (int j = 0; j < 16; j++) {
            const int nb = n0w + j * 8 + 2 * (ln & 3);
            const float2 bw0 = sBW[nb], bw1 = sBW[nb + 1];
            po[i][0] += fmaxf(fmaf(acc[i][j][0], INVWS, bw0.x), 0.f) * bw0.y
                      + fmaxf(fmaf(acc[i][j][1], INVWS, bw1.x), 0.f) * bw1.y;
            po[i][1] += fmaxf(fmaf(acc[i][j][2], INVWS, bw0.x), 0.f) * bw0.y
                      + fmaxf(fmaf(acc[i][j][3], INVWS, bw1.x), 0.f) * bw1.y;
        }
#pragma unroll
    for (int o = 1; o <= 2; o <<= 1)
#pragma unroll
        for (int i = 0; i < 2; i++) {
            po[i][0] += __shfl_xor_sync(0xffffffffu, po[i][0], o);
            po[i][1] += __shfl_xor_sync(0xffffffffu, po[i][1], o);
        }
    if ((ln & 3) == 0) {
        const int r = ln >> 2;
#pragma unroll
        for (int i = 0; i < 2; i++) {
            atomicAdd(&sred[m0w + i * 16 + r], po[i][0]);
            atomicAdd(&sred[m0w + i * 16 + 8 + r], po[i][1]);
        }
    }
    __syncthreads();
    if (tid < MT_) out[b * T_ + tid] = sred[tid] + bout[0];
}

extern "C" void kernel_launch(void* const* d_in, const int* in_sizes, int n_in,
                              void* d_out, int out_size) {
    const float* state  = (const float*)d_in[0];
    const float* action = (const float*)d_in[1];
    const float* Wk     = (const float*)d_in[2];
    const float* Wq     = (const float*)d_in[3];
    const float* Wv     = (const float*)d_in[4];
    const float* W1     = (const float*)d_in[5];
    const float* b1     = (const float*)d_in[6];
    const float* W2     = (const float*)d_in[7];
    const float* b2     = (const float*)d_in[8];
    const float* Wout   = (const float*)d_in[9];
    const float* bout   = (const float*)d_in[10];
    float* out = (float*)d_out;

    const int smem = MT_ * ASTRIDE * 2 + 2 * (2 * HID_ * KP_ * 2) +
                     2048 + 1024 + 512 + 512;  // ~203 KB
    cudaFuncSetAttribute(fused_kernel, cudaFuncAttributeMaxDynamicSharedMemorySize, smem);

    w2split_kernel<<<HID_ * HID_ / 256, 256>>>(W2);
    w1split_kernel<<<HID_ * 32 / 256, 256>>>(W1);
    fused_kernel<<<B_, 256, smem>>>(state, action, Wk, Wq, Wv,
                                    b1, b2, Wout, bout, out);
}

// round 9
// speedup vs baseline: 2.2291x; 1.0316x over previous
#include <cuda_runtime.h>
#include <cuda_fp16.h>
#include <cstdint>

typedef unsigned long long u64;

namespace {
constexpr int B_ = 256, T_ = 128, SD_ = 8, AD_ = 2, H_ = 3, K_ = 4, HID_ = 256;
constexpr int QD_ = SD_ + AD_;    // 10
constexpr int HK_ = H_ * K_;      // 12
constexpr int FEAT_ = HK_ + QD_;  // 22
constexpr int MT_ = 128;          // tokens per CTA = one batch
constexpr int KP_ = 64;           // main-GEMM K panel
constexpr int ASTRIDE = 264;      // fp16 elems per A row (256 + 8 pad) -> 528B
constexpr float WSCALE = 64.f;
constexpr float INVWS = 1.f / 64.f;
}

// pre-split weights (x64)
__device__ __half g_W2hi[HID_ * HID_];
__device__ __half g_W2lo[HID_ * HID_];
__device__ __half g_W1hi[HID_ * 32];   // [256][32], cols 22..31 zero
__device__ __half g_W1lo[HID_ * 32];

// ---------------- helpers ----------------
__device__ __forceinline__ uint32_t smem_u32(const void* p) {
    uint32_t a;
    asm("{ .reg .u64 t; cvta.to.shared.u64 t, %1; cvt.u32.u64 %0, t; }" : "=r"(a) : "l"(p));
    return a;
}
__device__ __forceinline__ void ldsm4(uint32_t r[4], uint32_t addr) {
    asm volatile("ldmatrix.sync.aligned.m8n8.x4.shared.b16 {%0,%1,%2,%3}, [%4];"
                 : "=r"(r[0]), "=r"(r[1]), "=r"(r[2]), "=r"(r[3]) : "r"(addr));
}
__device__ __forceinline__ void mma16816(float c[4], const uint32_t a[4],
                                         uint32_t b0, uint32_t b1) {
    asm volatile(
        "mma.sync.aligned.m16n8k16.row.col.f32.f16.f16.f32 "
        "{%0,%1,%2,%3}, {%4,%5,%6,%7}, {%8,%9}, {%0,%1,%2,%3};"
        : "+f"(c[0]), "+f"(c[1]), "+f"(c[2]), "+f"(c[3])
        : "r"(a[0]), "r"(a[1]), "r"(a[2]), "r"(a[3]), "r"(b0), "r"(b1));
}
__device__ __forceinline__ void cp_async16(uint32_t dst, const void* src) {
    asm volatile("cp.async.ca.shared.global [%0], [%1], 16;" :: "r"(dst), "l"(src) : "memory");
}
__device__ __forceinline__ uint32_t pack_half2(float lo, float hi) {
    __half2 h = __floats2half2_rn(lo, hi);
    return *(uint32_t*)&h;
}

// ---------------------------------------------------------------------------
// Prep (single kernel): W2*64 -> fp16 hi/lo (float4-vectorized, 1/thread);
// first 8 CTAs also split W1*64 (K padded 22 -> 32), 4 elems/thread.
// ---------------------------------------------------------------------------
__global__ __launch_bounds__(256) void wsplit_kernel(const float* __restrict__ W2,
                                                     const float* __restrict__ W1) {
    const int gid = blockIdx.x * 256 + threadIdx.x;   // 16384 threads
    {
        const float4 w4 = ((const float4*)W2)[gid];
        const float v[4] = {w4.x * WSCALE, w4.y * WSCALE, w4.z * WSCALE, w4.w * WSCALE};
        __half hi[4], lo[4];
#pragma unroll
        for (int j = 0; j < 4; j++) {
            hi[j] = __float2half_rn(v[j]);
            lo[j] = __float2half_rn(v[j] - __half2float(hi[j]));
        }
        ((__half2*)g_W2hi)[gid * 2]     = __halves2half2(hi[0], hi[1]);
        ((__half2*)g_W2hi)[gid * 2 + 1] = __halves2half2(hi[2], hi[3]);
        ((__half2*)g_W2lo)[gid * 2]     = __halves2half2(lo[0], lo[1]);
        ((__half2*)g_W2lo)[gid * 2 + 1] = __halves2half2(lo[2], lo[3]);
    }
    if (gid < 2048) {  // W1: 8192 elements, 4 per thread
#pragma unroll
        for (int j = 0; j < 4; j++) {
            const int i = gid * 4 + j;
            const int n = i >> 5, k = i & 31;
            const float w = (k < FEAT_) ? W1[n * FEAT_ + k] * WSCALE : 0.f;
            const __half hi = __float2half_rn(w);
            g_W1hi[i] = hi;
            g_W1lo[i] = __float2half_rn(w - __half2float(hi));
        }
    }
}

// ---------------------------------------------------------------------------
// Fused kernel: one CTA = one batch (128 tokens), 256 threads, 8 warps.
//   phase 0: attention (2-way jj split), feat written as fp16 hi/lo tile.
//   phase 1: h1 via HMMA (3-term, K=32), relu(D/64+b1) -> fp16 -> A tile.
//   phase 2: main HMMA D = A@(64*W2)hi^T + A@(64*W2)lo^T, 4 K-panels of 64,
//            double-buffered cp.async. Warps tiled 2(M) x 4(N), tile 64x64
//            (halves ldsm count vs 4x2: A dup 2x, B dup 2x).
//   epilogue: h2 = D/64 + b2; relu; dot Wout; reduce; +bout.
// ---------------------------------------------------------------------------
__global__ __launch_bounds__(256) void fused_kernel(
    const float* __restrict__ state, const float* __restrict__ action,
    const float* __restrict__ Wk, const float* __restrict__ Wq,
    const float* __restrict__ Wv,
    const float* __restrict__ b1, const float* __restrict__ b2,
    const float* __restrict__ Wout, const float* __restrict__ bout,
    float* __restrict__ out)
{
    extern __shared__ char smem[];
    constexpr int ABYTES = MT_ * ASTRIDE * 2;          // 67584
    constexpr int OFF_A  = 0;
    constexpr int OFF_B  = ABYTES;
    constexpr int BPANEL = HID_ * KP_ * 2;             // 32768
    constexpr int BUFSZ  = 2 * BPANEL;                 // 65536
    // buf1 region aliases (dead until main panel 1 staged):
    constexpr int OFF_W1T = OFF_B + BUFSZ;             // W1 hi 16384 | lo 16384
    constexpr int OFF_FH  = OFF_W1T + 32768;           // feat hi [128][64B] = 8192
    constexpr int OFF_FL  = OFF_FH + 8192;             // feat lo 8192
    constexpr int OFF_BW  = OFF_B + 2 * BUFSZ;         // float2 x 256 = 2048
    constexpr int OFF_B1  = OFF_BW + 2048;             // float x 256
    constexpr int OFF_RED = OFF_B1 + 1024;             // float x 128
    // aliases inside A region (dead until phase 1 writes A)
    constexpr int OFF_SK = 0, OFF_SV = 6144, OFF_PART = 12288;

    const uint32_t sb = smem_u32(smem);
    const int tid = threadIdx.x, wid = tid >> 5, ln = tid & 31;
    const int b = blockIdx.x;

    float2* sBW = (float2*)(smem + OFF_BW);
    float* sB1 = (float*)(smem + OFF_B1);
    float* sred = (float*)(smem + OFF_RED);
    float (*sK)[HK_] = (float(*)[HK_])(smem + OFF_SK);
    float (*sV)[HK_] = (float(*)[HK_])(smem + OFF_SV);
    float (*sPA)[MT_] = (float(*)[MT_])(smem + OFF_PART);

    // ---- stage main B panel p into buffer buf (128B rows, XOR-16B swizzle) ----
    const int srow0 = tid >> 3, sc = tid & 7;
    const int scx = (sc ^ (srow0 & 7)) << 4;           // row&7 constant across j
    auto stageB = [&](int p, int buf) {
        const uint32_t dbase = sb + OFF_B + (uint32_t)(buf * BUFSZ + scx);
        const __half* shi = g_W2hi + srow0 * HID_ + p * KP_ + sc * 8;
#pragma unroll
        for (int j = 0; j < 8; j++) {
            const uint32_t dst = dbase + (uint32_t)((srow0 + j * 32) * 128);
            cp_async16(dst, shi + j * 32 * HID_);
            cp_async16(dst + BPANEL, shi + j * 32 * HID_ + (HID_ * HID_ /*lo*/ - 0) * 0 +
                       0);  // placeholder (overwritten below)
        }
        asm volatile("cp.async.commit_group;" ::: "memory");
    };
    // NOTE: lambda above mis-structured for lo; use explicit version:
    auto stageB2 = [&](int p, int buf) {
        const uint32_t dbase = sb + OFF_B + (uint32_t)(buf * BUFSZ + scx);
        const int goff = srow0 * HID_ + p * KP_ + sc * 8;
#pragma unroll
        for (int j = 0; j < 8; j++) {
            const uint32_t dst = dbase + (uint32_t)((srow0 + j * 32) * 128);
            cp_async16(dst, g_W2hi + goff + j * 32 * HID_);
            cp_async16(dst + BPANEL, g_W2lo + goff + j * 32 * HID_);
        }
        asm volatile("cp.async.commit_group;" ::: "memory");
    };
    (void)stageB;
    stageB2(0, 0);
    // stage W1 tiles (64B rows, chunk c ^= (row>>1)&3)
    for (int it = tid; it < 2048; it += 256) {
        const int hl = it >> 10, idx = it & 1023, row = idx >> 2, c = idx & 3;
        const uint32_t dst = sb + OFF_W1T + (uint32_t)(hl * 16384 + row * 64 +
                                                       ((c ^ ((row >> 1) & 3)) << 4));
        cp_async16(dst, (hl ? g_W1lo : g_W1hi) + row * 32 + c * 8);
    }
    asm volatile("cp.async.commit_group;" ::: "memory");

    // zero feat tiles (pad cols 22..31 stay 0)
    {
        float4* z = (float4*)(smem + OFF_FH);
#pragma unroll
        for (int i = 0; i < 4; i++) z[tid + i * 256] = make_float4(0.f, 0.f, 0.f, 0.f);
    }
    sBW[tid] = make_float2(b2[tid], Wout[tid]);
    sB1[tid] = b1[tid];
    if (tid < MT_) sred[tid] = 0.f;

    // ---- phase 0: attention ----
    const int half = tid >> 7, t = tid & 127;
    float qs[QD_], q[HK_], kp[HK_], vp[HK_];
    {
        const float* st = state + (size_t)(b * T_ + t) * SD_;
        const float* ac = action + (size_t)(b * T_ + t) * AD_;
#pragma unroll
        for (int c = 0; c < SD_; c++) qs[c] = st[c];
        qs[SD_] = ac[0];
        qs[SD_ + 1] = ac[1];
#pragma unroll
        for (int i = 0; i < HK_; i++) {
            float a = 0.f;
#pragma unroll
            for (int c = 0; c < QD_; c++) a = fmaf(qs[c], Wq[i * QD_ + c], a);
            q[i] = a;
        }
#pragma unroll
        for (int i = 0; i < HK_; i++) {
            float ak = 0.f, av = 0.f;
#pragma unroll
            for (int c = 0; c < K_; c++) {
                ak = fmaf(qs[c], Wk[i * K_ + c], ak);
                av = fmaf(qs[c], Wv[i * K_ + c], av);
            }
            kp[i] = ak; vp[i] = av;
        }
        if (half == 0) {
#pragma unroll
            for (int i = 0; i < HK_; i++) { sK[t][i] = kp[i]; sV[t][i] = vp[i]; }
        }
    }
    __syncthreads();

    {
        float sum0 = 0.f, sum1 = 0.f, sum2 = 0.f;
        float acc[HK_];
#pragma unroll
        for (int i = 0; i < HK_; i++) acc[i] = 0.f;
        const int j0 = half * 64;
#pragma unroll 4
        for (int jx = 0; jx < 64; jx++) {
            const int jj = j0 + jx;
            const float4 k0 = *(const float4*)&sK[jj][0];
            const float4 k1 = *(const float4*)&sK[jj][4];
            const float4 k2 = *(const float4*)&sK[jj][8];
            float s0 = q[0]*k0.x + q[1]*k0.y + q[2]*k0.z + q[3]*k0.w;
            float s1 = q[4]*k1.x + q[5]*k1.y + q[6]*k1.z + q[7]*k1.w;
            float s2 = q[8]*k2.x + q[9]*k2.y + q[10]*k2.z + q[11]*k2.w;
            const float e0 = __expf(0.5f * s0);
            const float e1 = __expf(0.5f * s1);
            const float e2 = __expf(0.5f * s2);
            sum0 += e0; sum1 += e1; sum2 += e2;
            const float4 v0 = *(const float4*)&sV[jj][0];
            const float4 v1 = *(const float4*)&sV[jj][4];
            const float4 v2 = *(const float4*)&sV[jj][8];
            acc[0]  = fmaf(e0, v0.x, acc[0]);  acc[1]  = fmaf(e0, v0.y, acc[1]);
            acc[2]  = fmaf(e0, v0.z, acc[2]);  acc[3]  = fmaf(e0, v0.w, acc[3]);
            acc[4]  = fmaf(e1, v1.x, acc[4]);  acc[5]  = fmaf(e1, v1.y, acc[5]);
            acc[6]  = fmaf(e1, v1.z, acc[6]);  acc[7]  = fmaf(e1, v1.w, acc[7]);
            acc[8]  = fmaf(e2, v2.x, acc[8]);  acc[9]  = fmaf(e2, v2.y, acc[9]);
            acc[10] = fmaf(e2, v2.z, acc[10]); acc[11] = fmaf(e2, v2.w, acc[11]);
        }
        if (half == 1) {
            sPA[0][t] = sum0; sPA[1][t] = sum1; sPA[2][t] = sum2;
#pragma unroll
            for (int i = 0; i < HK_; i++) sPA[3 + i][t] = acc[i];
        }
        __syncthreads();
        if (half == 0) {
            sum0 += sPA[0][t]; sum1 += sPA[1][t]; sum2 += sPA[2][t];
#pragma unroll
            for (int i = 0; i < HK_; i++) acc[i] += sPA[3 + i][t];
            float s0 = q[0]*kp[0] + q[1]*kp[1] + q[2]*kp[2] + q[3]*kp[3];
            float s1 = q[4]*kp[4] + q[5]*kp[5] + q[6]*kp[6] + q[7]*kp[7];
            float s2 = q[8]*kp[8] + q[9]*kp[9] + q[10]*kp[10] + q[11]*kp[11];
            const float e0 = __expf(0.5f * s0);
            const float e1 = __expf(0.5f * s1);
            const float e2 = __expf(0.5f * s2);
            sum0 -= e0; sum1 -= e1; sum2 -= e2;
            const float i0 = 1.f / sum0, i1 = 1.f / sum1, i2 = 1.f / sum2;
            float f[FEAT_];
#pragma unroll
            for (int k = 0; k < K_; k++) {
                f[k]     = fmaf(-e0, vp[k],     acc[k])     * i0 - vp[k];
                f[4 + k] = fmaf(-e1, vp[4 + k], acc[4 + k]) * i1 - vp[4 + k];
                f[8 + k] = fmaf(-e2, vp[8 + k], acc[8 + k]) * i2 - vp[8 + k];
            }
#pragma unroll
            for (int c = 0; c < QD_; c++) f[HK_ + c] = qs[c];
            // write feat as fp16 hi/lo into swizzled [128][32] tiles
#pragma unroll
            for (int c = 0; c < FEAT_; c++) {
                const float v = f[c];
                const __half hi = __float2half_rn(v);
                const float lo = v - __half2float(hi);
                const uint32_t ad = (uint32_t)(t * 64 + (((c >> 3) ^ ((t >> 1) & 3)) << 4) +
                                               (c & 7) * 2);
                *(__half*)(smem + OFF_FH + ad) = hi;
                *(__half*)(smem + OFF_FL + ad) = __float2half_rn(lo);
            }
        }
    }
    asm volatile("cp.async.wait_group 0;" ::: "memory");
    __syncthreads();

    // ---- warp tiling: 2(M) x 4(N), warp tile 64x64 ----
    const int mwarp = wid >> 2, nwarp = wid & 3;
    const int m0w = mwarp * 64, n0w = nwarp * 64;
    const int rsel = (ln & 7) | (((ln >> 4) & 1) << 3);
    const int cpart = (ln >> 3) & 1;

    float acc[4][8][4];
#pragma unroll
    for (int i = 0; i < 4; i++)
#pragma unroll
        for (int j = 0; j < 8; j++)
#pragma unroll
            for (int c = 0; c < 4; c++) acc[i][j][c] = 0.f;

    // ---- phase 1: W1 HMMA (3-term, K=32) ----
    {
        const int aRow = m0w + (ln & 15);
        const int aSw = (aRow >> 1) & 3;
        const int aCS = ln >> 4;
        const int bSw = (rsel >> 1) & 3;
#pragma unroll
        for (int ks = 0; ks < 2; ks++) {
            uint32_t ah[4][4], al[4][4];
#pragma unroll
            for (int i = 0; i < 4; i++) {
                const uint32_t ad = sb + OFF_FH + (uint32_t)((aRow + i * 16) * 64 +
                                    (((ks * 2 + aCS) ^ aSw) << 4));
                ldsm4(ah[i], ad);
                ldsm4(al[i], ad + 8192);  // lo tile
            }
#pragma unroll
            for (int j = 0; j < 4; j++) {
                const uint32_t bd = sb + OFF_W1T + (uint32_t)((n0w + j * 16 + rsel) * 64 +
                                    (((ks * 2 + cpart) ^ bSw) << 4));
                uint32_t bh[4], bl[4];
                ldsm4(bh, bd);
                ldsm4(bl, bd + 16384);
#pragma unroll
                for (int i = 0; i < 4; i++) {
                    mma16816(acc[i][2 * j],     ah[i], bh[0], bh[1]);
                    mma16816(acc[i][2 * j + 1], ah[i], bh[2], bh[3]);
                    mma16816(acc[i][2 * j],     ah[i], bl[0], bl[1]);
                    mma16816(acc[i][2 * j + 1], ah[i], bl[2], bl[3]);
                    mma16816(acc[i][2 * j],     al[i], bh[0], bh[1]);
                    mma16816(acc[i][2 * j + 1], al[i], bh[2], bh[3]);
                }
            }
        }
        // h1 = relu(D/64 + b1) -> fp16 -> main A tile (row-major, padded stride)
#pragma unroll
        for (int i = 0; i < 4; i++) {
            const int r0 = m0w + i * 16 + (ln >> 2);
#pragma unroll
            for (int j = 0; j < 8; j++) {
                const int n = n0w + j * 8 + 2 * (ln & 3);
                const float h0 = fmaxf(fmaf(acc[i][j][0], INVWS, sB1[n]), 0.f);
                const float h1v = fmaxf(fmaf(acc[i][j][1], INVWS, sB1[n + 1]), 0.f);
                const float h2 = fmaxf(fmaf(acc[i][j][2], INVWS, sB1[n]), 0.f);
                const float h3 = fmaxf(fmaf(acc[i][j][3], INVWS, sB1[n + 1]), 0.f);
                *(uint32_t*)(smem + OFF_A + r0 * (ASTRIDE * 2) + n * 2) = pack_half2(h0, h1v);
                *(uint32_t*)(smem + OFF_A + (r0 + 8) * (ASTRIDE * 2) + n * 2) = pack_half2(h2, h3);
            }
        }
    }
    __syncthreads();

    // ---- phase 2: main 2-term HMMA GEMM, 4 K-panels, double-buffered ----
#pragma unroll
    for (int i = 0; i < 4; i++)
#pragma unroll
        for (int j = 0; j < 8; j++)
#pragma unroll
            for (int c = 0; c < 4; c++) acc[i][j][c] = 0.f;

    const uint32_t aBase = sb + OFF_A +
        (uint32_t)((m0w + (ln & 15)) * (ASTRIDE * 2) + (ln >> 4) * 16);
    const int swz = ln & 7;
    const uint32_t bRow = (uint32_t)((n0w + rsel) * 128);

    for (int p = 0; p < 4; p++) {
        if (p < 3) {
            stageB2(p + 1, (p + 1) & 1);
            asm volatile("cp.async.wait_group 1;" ::: "memory");
        } else {
            asm volatile("cp.async.wait_group 0;" ::: "memory");
        }
        __syncthreads();

        const uint32_t bBase = sb + OFF_B + (uint32_t)((p & 1) * BUFSZ) + bRow;

#pragma unroll
        for (int ks = 0; ks < 4; ks++) {
            uint32_t ah[4][4];
            const uint32_t ka = (uint32_t)(p * 128 + ks * 32);
#pragma unroll
            for (int i = 0; i < 4; i++)
                ldsm4(ah[i], aBase + ka + (uint32_t)(i * 16 * ASTRIDE * 2));
            const uint32_t bchunk = (uint32_t)(((ks * 2 + cpart) ^ swz) << 4);
#pragma unroll
            for (int jj = 0; jj < 4; jj++) {
                uint32_t bh[4], bl[4];
                const uint32_t bo = bchunk + (uint32_t)(jj * 16 * 128);
                ldsm4(bh, bBase + bo);
                ldsm4(bl, bBase + BPANEL + bo);
#pragma unroll
                for (int i = 0; i < 4; i++) {
                    mma16816(acc[i][2 * jj],     ah[i], bh[0], bh[1]);
                    mma16816(acc[i][2 * jj + 1], ah[i], bh[2], bh[3]);
                    mma16816(acc[i][2 * jj],     ah[i], bl[0], bl[1]);
                    mma16816(acc[i][2 * jj + 1], ah[i], bl[2], bl[3]);
                }
            }
        }
        __syncthreads();
    }

    // ---- epilogue: h2 = acc/64 + b2; relu; dot Wout; reduce ----
    float po[4][2] = {{0.f, 0.f}, {0.f, 0.f}, {0.f, 0.f}, {0.f, 0.f}};
#pragma unroll
    for (int i = 0; i < 4; i++)
#pragma unroll
        for (int j = 0; j < 8; j++) {
            const int nb = n0w + j * 8 + 2 * (ln & 3);
            const float2 bw0 = sBW[nb], bw1 = sBW[nb + 1];
            po[i][0] += fmaxf(fmaf(acc[i][j][0], INVWS, bw0.x), 0.f) * bw0.y
                      + fmaxf(fmaf(acc[i][j][1], INVWS, bw1.x), 0.f) * bw1.y;
            po[i][1] += fmaxf(fmaf(acc[i][j][2], INVWS, bw0.x), 0.f) * bw0.y
                      + fmaxf(fmaf(acc[i][j][3], INVWS, bw1.x), 0.f) * bw1.y;
        }
#pragma unroll
    for (int o = 1; o <= 2; o <<= 1)
#pragma unroll
        for (int i = 0; i < 4; i++) {
            po[i][0] += __shfl_xor_sync(0xffffffffu, po[i][0], o);
            po[i][1] += __shfl_xor_sync(0xffffffffu, po[i][1], o);
        }
    if ((ln & 3) == 0) {
        const int r = ln >> 2;
#pragma unroll
        for (int i = 0; i < 4; i++) {
            atomicAdd(&sred[m0w + i * 16 + r], po[i][0]);
            atomicAdd(&sred[m0w + i * 16 + 8 + r], po[i][1]);
        }
    }
    __syncthreads();
    if (tid < MT_) out[b * T_ + tid] = sred[tid] + bout[0];
}

extern "C" void kernel_launch(void* const* d_in, const int* in_sizes, int n_in,
                              void* d_out, int out_size) {
    const float* state  = (const float*)d_in[0];
    const float* action = (const float*)d_in[1];
    const float* Wk     = (const float*)d_in[2];
    const float* Wq     = (const float*)d_in[3];
    const float* Wv     = (const float*)d_in[4];
    const float* W1     = (const float*)d_in[5];
    const float* b1     = (const float*)d_in[6];
    const float* W2     = (const float*)d_in[7];
    const float* b2     = (const float*)d_in[8];
    const float* Wout   = (const float*)d_in[9];
    const float* bout   = (const float*)d_in[10];
    float* out = (float*)d_out;

    const int smem = MT_ * ASTRIDE * 2 + 2 * (2 * HID_ * KP_ * 2) +
                     2048 + 1024 + 512 + 512;  // ~203 KB
    cudaFuncSetAttribute(fused_kernel, cudaFuncAttributeMaxDynamicSharedMemorySize, smem);

    wsplit_kernel<<<64, 256>>>(W2, W1);
    fused_kernel<<<B_, 256, smem>>>(state, action, Wk, Wq, Wv,
                                    b1, b2, Wout, bout, out);
}

// round 10
// speedup vs baseline: 2.9245x; 1.3119x over previous
#include <cuda_runtime.h>
#include <cuda_fp16.h>
#include <cstdint>

typedef unsigned long long u64;

namespace {
constexpr int B_ = 256, T_ = 128, SD_ = 8, AD_ = 2, H_ = 3, K_ = 4, HID_ = 256;
constexpr int QD_ = SD_ + AD_;    // 10
constexpr int HK_ = H_ * K_;      // 12
constexpr int FEAT_ = HK_ + QD_;  // 22
constexpr int MT_ = 128;          // tokens per CTA = one batch
constexpr int KP_ = 64;           // main-GEMM K panel
constexpr int ASTRIDE = 264;      // fp16 elems per A row (256 + 8 pad) -> 528B
constexpr float WSCALE = 64.f;    // W1 path only
constexpr float INVWS = 1.f / 64.f;
}

// pre-split weights
__device__ __half g_W2h[HID_ * HID_];   // fp16(W2), unscaled, single term
__device__ __half g_W1hi[HID_ * 32];    // fp16 hi of 64*W1, K padded 22->32
__device__ __half g_W1lo[HID_ * 32];

// ---------------- helpers ----------------
__device__ __forceinline__ uint32_t smem_u32(const void* p) {
    uint32_t a;
    asm("{ .reg .u64 t; cvta.to.shared.u64 t, %1; cvt.u32.u64 %0, t; }" : "=r"(a) : "l"(p));
    return a;
}
__device__ __forceinline__ void ldsm4(uint32_t r[4], uint32_t addr) {
    asm volatile("ldmatrix.sync.aligned.m8n8.x4.shared.b16 {%0,%1,%2,%3}, [%4];"
                 : "=r"(r[0]), "=r"(r[1]), "=r"(r[2]), "=r"(r[3]) : "r"(addr));
}
__device__ __forceinline__ void mma16816(float c[4], const uint32_t a[4],
                                         uint32_t b0, uint32_t b1) {
    asm volatile(
        "mma.sync.aligned.m16n8k16.row.col.f32.f16.f16.f32 "
        "{%0,%1,%2,%3}, {%4,%5,%6,%7}, {%8,%9}, {%0,%1,%2,%3};"
        : "+f"(c[0]), "+f"(c[1]), "+f"(c[2]), "+f"(c[3])
        : "r"(a[0]), "r"(a[1]), "r"(a[2]), "r"(a[3]), "r"(b0), "r"(b1));
}
__device__ __forceinline__ void cp_async16(uint32_t dst, const void* src) {
    asm volatile("cp.async.ca.shared.global [%0], [%1], 16;" :: "r"(dst), "l"(src) : "memory");
}
__device__ __forceinline__ uint32_t pack_half2(float lo, float hi) {
    __half2 h = __floats2half2_rn(lo, hi);
    return *(uint32_t*)&h;
}

// ---------------------------------------------------------------------------
// Prep: W2 -> fp16 (vectorized); first 2048 threads also split 64*W1 hi/lo.
// ---------------------------------------------------------------------------
__global__ __launch_bounds__(256) void wsplit_kernel(const float* __restrict__ W2,
                                                     const float* __restrict__ W1) {
    const int gid = blockIdx.x * 256 + threadIdx.x;   // 16384 threads
    {
        const float4 w4 = ((const float4*)W2)[gid];
        ((__half2*)g_W2h)[gid * 2]     = __floats2half2_rn(w4.x, w4.y);
        ((__half2*)g_W2h)[gid * 2 + 1] = __floats2half2_rn(w4.z, w4.w);
    }
    if (gid < 2048) {  // W1: 8192 elements, 4 per thread
#pragma unroll
        for (int j = 0; j < 4; j++) {
            const int i = gid * 4 + j;
            const int n = i >> 5, k = i & 31;
            const float w = (k < FEAT_) ? W1[n * FEAT_ + k] * WSCALE : 0.f;
            const __half hi = __float2half_rn(w);
            g_W1hi[i] = hi;
            g_W1lo[i] = __float2half_rn(w - __half2float(hi));
        }
    }
}

// ---------------------------------------------------------------------------
// Fused kernel: one CTA = one batch (128 tokens), 256 threads, 8 warps.
//   phase 0: attention (2-way jj split), feat written as fp16 hi/lo tile.
//   phase 1: h1 via HMMA (3-term, K=32), relu(D/64+b1) -> fp16 -> A tile.
//   phase 2: main HMMA D = A @ fp16(W2)^T (single term), 4 K-panels of 64,
//            double-buffered cp.async. Warps 2(M) x 4(N), tile 64x64.
//   epilogue: h2 = D + b2; relu; dot Wout; reduce; +bout.
// ---------------------------------------------------------------------------
__global__ __launch_bounds__(256) void fused_kernel(
    const float* __restrict__ state, const float* __restrict__ action,
    const float* __restrict__ Wk, const float* __restrict__ Wq,
    const float* __restrict__ Wv,
    const float* __restrict__ b1, const float* __restrict__ b2,
    const float* __restrict__ Wout, const float* __restrict__ bout,
    float* __restrict__ out)
{
    extern __shared__ char smem[];
    constexpr int ABYTES = MT_ * ASTRIDE * 2;          // 67584
    constexpr int OFF_A  = 0;
    constexpr int OFF_B  = ABYTES;                     // 2 bufs x 32768
    constexpr int BPANEL = HID_ * KP_ * 2;             // 32768 (hi only)
    constexpr int BUFSZ  = BPANEL;
    constexpr int OFF_W1T = OFF_B + 2 * BUFSZ;         // W1 hi 16384 | lo 16384
    constexpr int OFF_FH  = OFF_W1T + 32768;           // feat hi [128][64B] = 8192
    constexpr int OFF_FL  = OFF_FH + 8192;             // feat lo 8192
    constexpr int OFF_BW  = OFF_FL + 8192;             // float2 x 256 = 2048
    constexpr int OFF_B1  = OFF_BW + 2048;             // float x 256
    constexpr int OFF_RED = OFF_B1 + 1024;             // float x 128
    // aliases inside A region (dead until phase 1 writes A)
    constexpr int OFF_SK = 0, OFF_SV = 6144, OFF_PART = 12288;

    const uint32_t sb = smem_u32(smem);
    const int tid = threadIdx.x, wid = tid >> 5, ln = tid & 31;
    const int b = blockIdx.x;

    float2* sBW = (float2*)(smem + OFF_BW);
    float* sB1 = (float*)(smem + OFF_B1);
    float* sred = (float*)(smem + OFF_RED);
    float (*sK)[HK_] = (float(*)[HK_])(smem + OFF_SK);
    float (*sV)[HK_] = (float(*)[HK_])(smem + OFF_SV);
    float (*sPA)[MT_] = (float(*)[MT_])(smem + OFF_PART);

    // ---- stage main B panel p (hi only; 128B rows, XOR-16B swizzle) ----
    const int srow0 = tid >> 3, sc = tid & 7;
    const int scx = (sc ^ (srow0 & 7)) << 4;           // row&7 constant across j
    auto stageB = [&](int p, int buf) {
        const uint32_t dbase = sb + OFF_B + (uint32_t)(buf * BUFSZ + scx);
        const int goff = srow0 * HID_ + p * KP_ + sc * 8;
#pragma unroll
        for (int j = 0; j < 8; j++) {
            cp_async16(dbase + (uint32_t)((srow0 + j * 32) * 128),
                       g_W2h + goff + j * 32 * HID_);
        }
        asm volatile("cp.async.commit_group;" ::: "memory");
    };
    stageB(0, 0);
    // stage W1 tiles (64B rows, chunk c ^= (row>>1)&3)
    for (int it = tid; it < 2048; it += 256) {
        const int hl = it >> 10, idx = it & 1023, row = idx >> 2, c = idx & 3;
        const uint32_t dst = sb + OFF_W1T + (uint32_t)(hl * 16384 + row * 64 +
                                                       ((c ^ ((row >> 1) & 3)) << 4));
        cp_async16(dst, (hl ? g_W1lo : g_W1hi) + row * 32 + c * 8);
    }
    asm volatile("cp.async.commit_group;" ::: "memory");

    // zero feat tiles (pad cols 22..31 stay 0)
    {
        float4* z = (float4*)(smem + OFF_FH);
#pragma unroll
        for (int i = 0; i < 4; i++) z[tid + i * 256] = make_float4(0.f, 0.f, 0.f, 0.f);
    }
    sBW[tid] = make_float2(b2[tid], Wout[tid]);
    sB1[tid] = b1[tid];
    if (tid < MT_) sred[tid] = 0.f;

    // ---- phase 0: attention ----
    const int half = tid >> 7, t = tid & 127;
    float qs[QD_], q[HK_], kp[HK_], vp[HK_];
    {
        const float* st = state + (size_t)(b * T_ + t) * SD_;
        const float* ac = action + (size_t)(b * T_ + t) * AD_;
#pragma unroll
        for (int c = 0; c < SD_; c++) qs[c] = st[c];
        qs[SD_] = ac[0];
        qs[SD_ + 1] = ac[1];
#pragma unroll
        for (int i = 0; i < HK_; i++) {
            float a = 0.f;
#pragma unroll
            for (int c = 0; c < QD_; c++) a = fmaf(qs[c], Wq[i * QD_ + c], a);
            q[i] = a;
        }
#pragma unroll
        for (int i = 0; i < HK_; i++) {
            float ak = 0.f, av = 0.f;
#pragma unroll
            for (int c = 0; c < K_; c++) {
                ak = fmaf(qs[c], Wk[i * K_ + c], ak);
                av = fmaf(qs[c], Wv[i * K_ + c], av);
            }
            kp[i] = ak; vp[i] = av;
        }
        if (half == 0) {
#pragma unroll
            for (int i = 0; i < HK_; i++) { sK[t][i] = kp[i]; sV[t][i] = vp[i]; }
        }
    }
    __syncthreads();

    {
        float sum0 = 0.f, sum1 = 0.f, sum2 = 0.f;
        float acc[HK_];
#pragma unroll
        for (int i = 0; i < HK_; i++) acc[i] = 0.f;
        const int j0 = half * 64;
#pragma unroll 4
        for (int jx = 0; jx < 64; jx++) {
            const int jj = j0 + jx;
            const float4 k0 = *(const float4*)&sK[jj][0];
            const float4 k1 = *(const float4*)&sK[jj][4];
            const float4 k2 = *(const float4*)&sK[jj][8];
            float s0 = q[0]*k0.x + q[1]*k0.y + q[2]*k0.z + q[3]*k0.w;
            float s1 = q[4]*k1.x + q[5]*k1.y + q[6]*k1.z + q[7]*k1.w;
            float s2 = q[8]*k2.x + q[9]*k2.y + q[10]*k2.z + q[11]*k2.w;
            const float e0 = __expf(0.5f * s0);
            const float e1 = __expf(0.5f * s1);
            const float e2 = __expf(0.5f * s2);
            sum0 += e0; sum1 += e1; sum2 += e2;
            const float4 v0 = *(const float4*)&sV[jj][0];
            const float4 v1 = *(const float4*)&sV[jj][4];
            const float4 v2 = *(const float4*)&sV[jj][8];
            acc[0]  = fmaf(e0, v0.x, acc[0]);  acc[1]  = fmaf(e0, v0.y, acc[1]);
            acc[2]  = fmaf(e0, v0.z, acc[2]);  acc[3]  = fmaf(e0, v0.w, acc[3]);
            acc[4]  = fmaf(e1, v1.x, acc[4]);  acc[5]  = fmaf(e1, v1.y, acc[5]);
            acc[6]  = fmaf(e1, v1.z, acc[6]);  acc[7]  = fmaf(e1, v1.w, acc[7]);
            acc[8]  = fmaf(e2, v2.x, acc[8]);  acc[9]  = fmaf(e2, v2.y, acc[9]);
            acc[10] = fmaf(e2, v2.z, acc[10]); acc[11] = fmaf(e2, v2.w, acc[11]);
        }
        if (half == 1) {
            sPA[0][t] = sum0; sPA[1][t] = sum1; sPA[2][t] = sum2;
#pragma unroll
            for (int i = 0; i < HK_; i++) sPA[3 + i][t] = acc[i];
        }
        __syncthreads();
        if (half == 0) {
            sum0 += sPA[0][t]; sum1 += sPA[1][t]; sum2 += sPA[2][t];
#pragma unroll
            for (int i = 0; i < HK_; i++) acc[i] += sPA[3 + i][t];
            float s0 = q[0]*kp[0] + q[1]*kp[1] + q[2]*kp[2] + q[3]*kp[3];
            float s1 = q[4]*kp[4] + q[5]*kp[5] + q[6]*kp[6] + q[7]*kp[7];
            float s2 = q[8]*kp[8] + q[9]*kp[9] + q[10]*kp[10] + q[11]*kp[11];
            const float e0 = __expf(0.5f * s0);
            const float e1 = __expf(0.5f * s1);
            const float e2 = __expf(0.5f * s2);
            sum0 -= e0; sum1 -= e1; sum2 -= e2;
            const float i0 = 1.f / sum0, i1 = 1.f / sum1, i2 = 1.f / sum2;
            float f[FEAT_];
#pragma unroll
            for (int k = 0; k < K_; k++) {
                f[k]     = fmaf(-e0, vp[k],     acc[k])     * i0 - vp[k];
                f[4 + k] = fmaf(-e1, vp[4 + k], acc[4 + k]) * i1 - vp[4 + k];
                f[8 + k] = fmaf(-e2, vp[8 + k], acc[8 + k]) * i2 - vp[8 + k];
            }
#pragma unroll
            for (int c = 0; c < QD_; c++) f[HK_ + c] = qs[c];
            // write feat as fp16 hi/lo into swizzled [128][32] tiles
#pragma unroll
            for (int c = 0; c < FEAT_; c++) {
                const float v = f[c];
                const __half hi = __float2half_rn(v);
                const float lo = v - __half2float(hi);
                const uint32_t ad = (uint32_t)(t * 64 + (((c >> 3) ^ ((t >> 1) & 3)) << 4) +
                                               (c & 7) * 2);
                *(__half*)(smem + OFF_FH + ad) = hi;
                *(__half*)(smem + OFF_FL + ad) = __float2half_rn(lo);
            }
        }
    }
    asm volatile("cp.async.wait_group 0;" ::: "memory");
    __syncthreads();

    // ---- warp tiling: 2(M) x 4(N), warp tile 64x64 ----
    const int mwarp = wid >> 2, nwarp = wid & 3;
    const int m0w = mwarp * 64, n0w = nwarp * 64;
    const int rsel = (ln & 7) | (((ln >> 4) & 1) << 3);
    const int cpart = (ln >> 3) & 1;

    float acc[4][8][4];
#pragma unroll
    for (int i = 0; i < 4; i++)
#pragma unroll
        for (int j = 0; j < 8; j++)
#pragma unroll
            for (int c = 0; c < 4; c++) acc[i][j][c] = 0.f;

    // ---- phase 1: W1 HMMA (3-term, K=32) ----
    {
        const int aRow = m0w + (ln & 15);
        const int aSw = (aRow >> 1) & 3;
        const int aCS = ln >> 4;
        const int bSw = (rsel >> 1) & 3;
#pragma unroll
        for (int ks = 0; ks < 2; ks++) {
            uint32_t ah[4][4], al[4][4];
#pragma unroll
            for (int i = 0; i < 4; i++) {
                const uint32_t ad = sb + OFF_FH + (uint32_t)((aRow + i * 16) * 64 +
                                    (((ks * 2 + aCS) ^ aSw) << 4));
                ldsm4(ah[i], ad);
                ldsm4(al[i], ad + 8192);  // lo tile
            }
#pragma unroll
            for (int j = 0; j < 4; j++) {
                const uint32_t bd = sb + OFF_W1T + (uint32_t)((n0w + j * 16 + rsel) * 64 +
                                    (((ks * 2 + cpart) ^ bSw) << 4));
                uint32_t bh[4], bl[4];
                ldsm4(bh, bd);
                ldsm4(bl, bd + 16384);
#pragma unroll
                for (int i = 0; i < 4; i++) {
                    mma16816(acc[i][2 * j],     ah[i], bh[0], bh[1]);
                    mma16816(acc[i][2 * j + 1], ah[i], bh[2], bh[3]);
                    mma16816(acc[i][2 * j],     ah[i], bl[0], bl[1]);
                    mma16816(acc[i][2 * j + 1], ah[i], bl[2], bl[3]);
                    mma16816(acc[i][2 * j],     al[i], bh[0], bh[1]);
                    mma16816(acc[i][2 * j + 1], al[i], bh[2], bh[3]);
                }
            }
        }
        // h1 = relu(D/64 + b1) -> fp16 -> main A tile (row-major, padded stride)
#pragma unroll
        for (int i = 0; i < 4; i++) {
            const int r0 = m0w + i * 16 + (ln >> 2);
#pragma unroll
            for (int j = 0; j < 8; j++) {
                const int n = n0w + j * 8 + 2 * (ln & 3);
                const float h0 = fmaxf(fmaf(acc[i][j][0], INVWS, sB1[n]), 0.f);
                const float h1v = fmaxf(fmaf(acc[i][j][1], INVWS, sB1[n + 1]), 0.f);
                const float h2 = fmaxf(fmaf(acc[i][j][2], INVWS, sB1[n]), 0.f);
                const float h3 = fmaxf(fmaf(acc[i][j][3], INVWS, sB1[n + 1]), 0.f);
                *(uint32_t*)(smem + OFF_A + r0 * (ASTRIDE * 2) + n * 2) = pack_half2(h0, h1v);
                *(uint32_t*)(smem + OFF_A + (r0 + 8) * (ASTRIDE * 2) + n * 2) = pack_half2(h2, h3);
            }
        }
    }
    __syncthreads();

    // ---- phase 2: main single-term HMMA GEMM, 4 K-panels, double-buffered ----
#pragma unroll
    for (int i = 0; i < 4; i++)
#pragma unroll
        for (int j = 0; j < 8; j++)
#pragma unroll
            for (int c = 0; c < 4; c++) acc[i][j][c] = 0.f;

    const uint32_t aBase = sb + OFF_A +
        (uint32_t)((m0w + (ln & 15)) * (ASTRIDE * 2) + (ln >> 4) * 16);
    const int swz = ln & 7;
    const uint32_t bRow = (uint32_t)((n0w + rsel) * 128);

    for (int p = 0; p < 4; p++) {
        if (p < 3) {
            stageB(p + 1, (p + 1) & 1);
            asm volatile("cp.async.wait_group 1;" ::: "memory");
        } else {
            asm volatile("cp.async.wait_group 0;" ::: "memory");
        }
        __syncthreads();

        const uint32_t bBase = sb + OFF_B + (uint32_t)((p & 1) * BUFSZ) + bRow;

#pragma unroll
        for (int ks = 0; ks < 4; ks++) {
            uint32_t ah[4][4];
            const uint32_t ka = (uint32_t)(p * 128 + ks * 32);
#pragma unroll
            for (int i = 0; i < 4; i++)
                ldsm4(ah[i], aBase + ka + (uint32_t)(i * 16 * ASTRIDE * 2));
            const uint32_t bchunk = (uint32_t)(((ks * 2 + cpart) ^ swz) << 4);
#pragma unroll
            for (int jj = 0; jj < 4; jj++) {
                uint32_t bh[4];
                ldsm4(bh, bBase + bchunk + (uint32_t)(jj * 16 * 128));
#pragma unroll
                for (int i = 0; i < 4; i++) {
                    mma16816(acc[i][2 * jj],     ah[i], bh[0], bh[1]);
                    mma16816(acc[i][2 * jj + 1], ah[i], bh[2], bh[3]);
                }
            }
        }
        __syncthreads();
    }

    // ---- epilogue: h2 = acc + b2; relu; dot Wout; reduce ----
    float po[4][2] = {{0.f, 0.f}, {0.f, 0.f}, {0.f, 0.f}, {0.f, 0.f}};
#pragma unroll
    for (int i = 0; i < 4; i++)
#pragma unroll
        for (int j = 0; j < 8; j++) {
            const int nb = n0w + j * 8 + 2 * (ln & 3);
            const float2 bw0 = sBW[nb], bw1 = sBW[nb + 1];
            po[i][0] += fmaxf(acc[i][j][0] + bw0.x, 0.f) * bw0.y
                      + fmaxf(acc[i][j][1] + bw1.x, 0.f) * bw1.y;
            po[i][1] += fmaxf(acc[i][j][2] + bw0.x, 0.f) * bw0.y
                      + fmaxf(acc[i][j][3] + bw1.x, 0.f) * bw1.y;
        }
#pragma unroll
    for (int o = 1; o <= 2; o <<= 1)
#pragma unroll
        for (int i = 0; i < 4; i++) {
            po[i][0] += __shfl_xor_sync(0xffffffffu, po[i][0], o);
            po[i][1] += __shfl_xor_sync(0xffffffffu, po[i][1], o);
        }
    if ((ln & 3) == 0) {
        const int r = ln >> 2;
#pragma unroll
        for (int i = 0; i < 4; i++) {
            atomicAdd(&sred[m0w + i * 16 + r], po[i][0]);
            atomicAdd(&sred[m0w + i * 16 + 8 + r], po[i][1]);
        }
    }
    __syncthreads();
    if (tid < MT_) out[b * T_ + tid] = sred[tid] + bout[0];
}

extern "C" void kernel_launch(void* const* d_in, const int* in_sizes, int n_in,
                              void* d_out, int out_size) {
    const float* state  = (const float*)d_in[0];
    const float* action = (const float*)d_in[1];
    const float* Wk     = (const float*)d_in[2];
    const float* Wq     = (const float*)d_in[3];
    const float* Wv     = (const float*)d_in[4];
    const float* W1     = (const float*)d_in[5];
    const float* b1     = (const float*)d_in[6];
    const float* W2     = (const float*)d_in[7];
    const float* b2     = (const float*)d_in[8];
    const float* Wout   = (const float*)d_in[9];
    const float* bout   = (const float*)d_in[10];
    float* out = (float*)d_out;

    const int smem = MT_ * ASTRIDE * 2          // A tile          67584
                   + 2 * (HID_ * KP_ * 2)       // B double buffer 65536
                   + 32768                      // W1 tiles
                   + 16384                      // feat hi/lo
                   + 2048 + 1024 + 512;         // bw, b1, red     -> 185856
    cudaFuncSetAttribute(fused_kernel, cudaFuncAttributeMaxDynamicSharedMemorySize, smem);

    wsplit_kernel<<<64, 256>>>(W2, W1);
    fused_kernel<<<B_, 256, smem>>>(state, action, Wk, Wq, Wv,
                                    b1, b2, Wout, bout, out);
}

// round 11
// speedup vs baseline: 3.0822x; 1.0539x over previous
#include <cuda_runtime.h>
#include <cuda_fp16.h>
#include <cstdint>

typedef unsigned long long u64;

namespace {
constexpr int B_ = 256, T_ = 128, SD_ = 8, AD_ = 2, H_ = 3, K_ = 4, HID_ = 256;
constexpr int QD_ = SD_ + AD_;    // 10
constexpr int HK_ = H_ * K_;      // 12
constexpr int FEAT_ = HK_ + QD_;  // 22
constexpr int MT_ = 128;          // tokens per CTA = one batch
constexpr int KP_ = 64;           // main-GEMM K panel
constexpr int ASTRIDE = 264;      // fp16 elems per A row (256 + 8 pad) -> 528B
}

// pre-converted fp16 weights (single term each)
__device__ __half g_W2h[HID_ * HID_];
__device__ __half g_W1h[HID_ * 32];     // [256][32], cols 22..31 zero

// ---------------- helpers ----------------
__device__ __forceinline__ uint32_t smem_u32(const void* p) {
    uint32_t a;
    asm("{ .reg .u64 t; cvta.to.shared.u64 t, %1; cvt.u32.u64 %0, t; }" : "=r"(a) : "l"(p));
    return a;
}
__device__ __forceinline__ void ldsm4(uint32_t r[4], uint32_t addr) {
    asm volatile("ldmatrix.sync.aligned.m8n8.x4.shared.b16 {%0,%1,%2,%3}, [%4];"
                 : "=r"(r[0]), "=r"(r[1]), "=r"(r[2]), "=r"(r[3]) : "r"(addr));
}
__device__ __forceinline__ void mma16816(float c[4], const uint32_t a[4],
                                         uint32_t b0, uint32_t b1) {
    asm volatile(
        "mma.sync.aligned.m16n8k16.row.col.f32.f16.f16.f32 "
        "{%0,%1,%2,%3}, {%4,%5,%6,%7}, {%8,%9}, {%0,%1,%2,%3};"
        : "+f"(c[0]), "+f"(c[1]), "+f"(c[2]), "+f"(c[3])
        : "r"(a[0]), "r"(a[1]), "r"(a[2]), "r"(a[3]), "r"(b0), "r"(b1));
}
__device__ __forceinline__ void cp_async16(uint32_t dst, const void* src) {
    asm volatile("cp.async.ca.shared.global [%0], [%1], 16;" :: "r"(dst), "l"(src) : "memory");
}
__device__ __forceinline__ uint32_t pack_half2(float lo, float hi) {
    __half2 h = __floats2half2_rn(lo, hi);
    return *(uint32_t*)&h;
}

// ---------------------------------------------------------------------------
// Prep: W2 -> fp16 (vectorized); first 512 threads also convert W1 (pad 22->32).
// ---------------------------------------------------------------------------
__global__ __launch_bounds__(256) void wsplit_kernel(const float* __restrict__ W2,
                                                     const float* __restrict__ W1) {
    const int gid = blockIdx.x * 256 + threadIdx.x;   // 16384 threads
    {
        const float4 w4 = ((const float4*)W2)[gid];
        ((__half2*)g_W2h)[gid * 2]     = __floats2half2_rn(w4.x, w4.y);
        ((__half2*)g_W2h)[gid * 2 + 1] = __floats2half2_rn(w4.z, w4.w);
    }
    if (gid < 512) {  // W1: 8192 elements, 16 per thread
#pragma unroll
        for (int j = 0; j < 16; j++) {
            const int i = gid * 16 + j;
            const int n = i >> 5, k = i & 31;
            g_W1h[i] = __float2half_rn((k < FEAT_) ? W1[n * FEAT_ + k] : 0.f);
        }
    }
}

// ---------------------------------------------------------------------------
// Fused kernel: one CTA = one batch (128 tokens), 256 threads, 8 warps.
//   phase 0: attention (2-way jj split), feat written as single fp16 tile.
//   phase 1: h1 via HMMA (single term, K=32), relu(D+b1) -> fp16 -> A tile.
//   phase 2: main HMMA D = A @ fp16(W2)^T, 4 K-panels of 64, double-buffered
//            cp.async; per-ks fragments batched (8 ldsm then 32 MMAs).
//   epilogue: h2 = D + b2; relu; dot Wout; reduce; +bout.
// ---------------------------------------------------------------------------
__global__ __launch_bounds__(256) void fused_kernel(
    const float* __restrict__ state, const float* __restrict__ action,
    const float* __restrict__ Wk, const float* __restrict__ Wq,
    const float* __restrict__ Wv,
    const float* __restrict__ b1, const float* __restrict__ b2,
    const float* __restrict__ Wout, const float* __restrict__ bout,
    float* __restrict__ out)
{
    extern __shared__ char smem[];
    constexpr int ABYTES = MT_ * ASTRIDE * 2;          // 67584
    constexpr int OFF_A  = 0;
    constexpr int OFF_B  = ABYTES;                     // 2 bufs x 32768
    constexpr int BPANEL = HID_ * KP_ * 2;             // 32768
    constexpr int BUFSZ  = BPANEL;
    constexpr int OFF_W1T = OFF_B + 2 * BUFSZ;         // 16384 (single fp16)
    constexpr int OFF_FH  = OFF_W1T + 16384;           // feat [128][64B] = 8192
    constexpr int OFF_BW  = OFF_FH + 8192;             // float2 x 256 = 2048
    constexpr int OFF_B1  = OFF_BW + 2048;             // float x 256
    constexpr int OFF_RED = OFF_B1 + 1024;             // float x 128
    // aliases inside A region (dead until phase 1 writes A)
    constexpr int OFF_SK = 0, OFF_SV = 6144, OFF_PART = 12288;

    const uint32_t sb = smem_u32(smem);
    const int tid = threadIdx.x, wid = tid >> 5, ln = tid & 31;
    const int b = blockIdx.x;

    float2* sBW = (float2*)(smem + OFF_BW);
    float* sB1 = (float*)(smem + OFF_B1);
    float* sred = (float*)(smem + OFF_RED);
    float (*sK)[HK_] = (float(*)[HK_])(smem + OFF_SK);
    float (*sV)[HK_] = (float(*)[HK_])(smem + OFF_SV);
    float (*sPA)[MT_] = (float(*)[MT_])(smem + OFF_PART);

    // ---- stage main B panel p (128B rows, XOR-16B swizzle) ----
    const int srow0 = tid >> 3, sc = tid & 7;
    const int scx = (sc ^ (srow0 & 7)) << 4;           // row&7 constant across j
    auto stageB = [&](int p, int buf) {
        const uint32_t dbase = sb + OFF_B + (uint32_t)(buf * BUFSZ + scx);
        const int goff = srow0 * HID_ + p * KP_ + sc * 8;
#pragma unroll
        for (int j = 0; j < 8; j++) {
            cp_async16(dbase + (uint32_t)((srow0 + j * 32) * 128),
                       g_W2h + goff + j * 32 * HID_);
        }
        asm volatile("cp.async.commit_group;" ::: "memory");
    };
    stageB(0, 0);
    // stage W1 tile (64B rows, chunk c ^= (row>>1)&3)
    for (int it = tid; it < 1024; it += 256) {
        const int row = it >> 2, c = it & 3;
        const uint32_t dst = sb + OFF_W1T + (uint32_t)(row * 64 +
                                                       ((c ^ ((row >> 1) & 3)) << 4));
        cp_async16(dst, g_W1h + row * 32 + c * 8);
    }
    asm volatile("cp.async.commit_group;" ::: "memory");

    // zero feat tile (pad cols 22..31 stay 0): 8192 B = 512 float4
    {
        float4* z = (float4*)(smem + OFF_FH);
#pragma unroll
        for (int i = 0; i < 2; i++) z[tid + i * 256] = make_float4(0.f, 0.f, 0.f, 0.f);
    }
    sBW[tid] = make_float2(b2[tid], Wout[tid]);
    sB1[tid] = b1[tid];
    if (tid < MT_) sred[tid] = 0.f;

    // ---- phase 0: attention ----
    const int half = tid >> 7, t = tid & 127;
    float qs[QD_], q[HK_], kp[HK_], vp[HK_];
    {
        const float* st = state + (size_t)(b * T_ + t) * SD_;
        const float* ac = action + (size_t)(b * T_ + t) * AD_;
#pragma unroll
        for (int c = 0; c < SD_; c++) qs[c] = st[c];
        qs[SD_] = ac[0];
        qs[SD_ + 1] = ac[1];
#pragma unroll
        for (int i = 0; i < HK_; i++) {
            float a = 0.f;
#pragma unroll
            for (int c = 0; c < QD_; c++) a = fmaf(qs[c], Wq[i * QD_ + c], a);
            q[i] = a;
        }
#pragma unroll
        for (int i = 0; i < HK_; i++) {
            float ak = 0.f, av = 0.f;
#pragma unroll
            for (int c = 0; c < K_; c++) {
                ak = fmaf(qs[c], Wk[i * K_ + c], ak);
                av = fmaf(qs[c], Wv[i * K_ + c], av);
            }
            kp[i] = ak; vp[i] = av;
        }
        if (half == 0) {
#pragma unroll
            for (int i = 0; i < HK_; i++) { sK[t][i] = kp[i]; sV[t][i] = vp[i]; }
        }
    }
    __syncthreads();

    {
        float sum0 = 0.f, sum1 = 0.f, sum2 = 0.f;
        float acc[HK_];
#pragma unroll
        for (int i = 0; i < HK_; i++) acc[i] = 0.f;
        const int j0 = half * 64;
#pragma unroll 4
        for (int jx = 0; jx < 64; jx++) {
            const int jj = j0 + jx;
            const float4 k0 = *(const float4*)&sK[jj][0];
            const float4 k1 = *(const float4*)&sK[jj][4];
            const float4 k2 = *(const float4*)&sK[jj][8];
            float s0 = q[0]*k0.x + q[1]*k0.y + q[2]*k0.z + q[3]*k0.w;
            float s1 = q[4]*k1.x + q[5]*k1.y + q[6]*k1.z + q[7]*k1.w;
            float s2 = q[8]*k2.x + q[9]*k2.y + q[10]*k2.z + q[11]*k2.w;
            const float e0 = __expf(0.5f * s0);
            const float e1 = __expf(0.5f * s1);
            const float e2 = __expf(0.5f * s2);
            sum0 += e0; sum1 += e1; sum2 += e2;
            const float4 v0 = *(const float4*)&sV[jj][0];
            const float4 v1 = *(const float4*)&sV[jj][4];
            const float4 v2 = *(const float4*)&sV[jj][8];
            acc[0]  = fmaf(e0, v0.x, acc[0]);  acc[1]  = fmaf(e0, v0.y, acc[1]);
            acc[2]  = fmaf(e0, v0.z, acc[2]);  acc[3]  = fmaf(e0, v0.w, acc[3]);
            acc[4]  = fmaf(e1, v1.x, acc[4]);  acc[5]  = fmaf(e1, v1.y, acc[5]);
            acc[6]  = fmaf(e1, v1.z, acc[6]);  acc[7]  = fmaf(e1, v1.w, acc[7]);
            acc[8]  = fmaf(e2, v2.x, acc[8]);  acc[9]  = fmaf(e2, v2.y, acc[9]);
            acc[10] = fmaf(e2, v2.z, acc[10]); acc[11] = fmaf(e2, v2.w, acc[11]);
        }
        if (half == 1) {
            sPA[0][t] = sum0; sPA[1][t] = sum1; sPA[2][t] = sum2;
#pragma unroll
            for (int i = 0; i < HK_; i++) sPA[3 + i][t] = acc[i];
        }
        __syncthreads();
        if (half == 0) {
            sum0 += sPA[0][t]; sum1 += sPA[1][t]; sum2 += sPA[2][t];
#pragma unroll
            for (int i = 0; i < HK_; i++) acc[i] += sPA[3 + i][t];
            float s0 = q[0]*kp[0] + q[1]*kp[1] + q[2]*kp[2] + q[3]*kp[3];
            float s1 = q[4]*kp[4] + q[5]*kp[5] + q[6]*kp[6] + q[7]*kp[7];
            float s2 = q[8]*kp[8] + q[9]*kp[9] + q[10]*kp[10] + q[11]*kp[11];
            const float e0 = __expf(0.5f * s0);
            const float e1 = __expf(0.5f * s1);
            const float e2 = __expf(0.5f * s2);
            sum0 -= e0; sum1 -= e1; sum2 -= e2;
            const float i0 = 1.f / sum0, i1 = 1.f / sum1, i2 = 1.f / sum2;
            float f[FEAT_];
#pragma unroll
            for (int k = 0; k < K_; k++) {
                f[k]     = fmaf(-e0, vp[k],     acc[k])     * i0 - vp[k];
                f[4 + k] = fmaf(-e1, vp[4 + k], acc[4 + k]) * i1 - vp[4 + k];
                f[8 + k] = fmaf(-e2, vp[8 + k], acc[8 + k]) * i2 - vp[8 + k];
            }
#pragma unroll
            for (int c = 0; c < QD_; c++) f[HK_ + c] = qs[c];
            // write feat as single fp16 into swizzled [128][32] tile
#pragma unroll
            for (int c = 0; c < FEAT_; c++) {
                const uint32_t ad = (uint32_t)(t * 64 + (((c >> 3) ^ ((t >> 1) & 3)) << 4) +
                                               (c & 7) * 2);
                *(__half*)(smem + OFF_FH + ad) = __float2half_rn(f[c]);
            }
        }
    }
    asm volatile("cp.async.wait_group 0;" ::: "memory");
    __syncthreads();

    // ---- warp tiling: 2(M) x 4(N), warp tile 64x64 ----
    const int mwarp = wid >> 2, nwarp = wid & 3;
    const int m0w = mwarp * 64, n0w = nwarp * 64;
    const int rsel = (ln & 7) | (((ln >> 4) & 1) << 3);
    const int cpart = (ln >> 3) & 1;

    float acc[4][8][4];
#pragma unroll
    for (int i = 0; i < 4; i++)
#pragma unroll
        for (int j = 0; j < 8; j++)
#pragma unroll
            for (int c = 0; c < 4; c++) acc[i][j][c] = 0.f;

    // ---- phase 1: W1 HMMA (single term, K=32) ----
    {
        const int aRow = m0w + (ln & 15);
        const int aSw = (aRow >> 1) & 3;
        const int aCS = ln >> 4;
        const int bSw = (rsel >> 1) & 3;
#pragma unroll
        for (int ks = 0; ks < 2; ks++) {
            uint32_t ah[4][4], bh[4][4];
#pragma unroll
            for (int i = 0; i < 4; i++)
                ldsm4(ah[i], sb + OFF_FH + (uint32_t)((aRow + i * 16) * 64 +
                              (((ks * 2 + aCS) ^ aSw) << 4)));
#pragma unroll
            for (int j = 0; j < 4; j++)
                ldsm4(bh[j], sb + OFF_W1T + (uint32_t)((n0w + j * 16 + rsel) * 64 +
                              (((ks * 2 + cpart) ^ bSw) << 4)));
#pragma unroll
            for (int j = 0; j < 4; j++)
#pragma unroll
                for (int i = 0; i < 4; i++) {
                    mma16816(acc[i][2 * j],     ah[i], bh[j][0], bh[j][1]);
                    mma16816(acc[i][2 * j + 1], ah[i], bh[j][2], bh[j][3]);
                }
        }
        // h1 = relu(D + b1) -> fp16 -> main A tile (row-major, padded stride)
#pragma unroll
        for (int i = 0; i < 4; i++) {
            const int r0 = m0w + i * 16 + (ln >> 2);
#pragma unroll
            for (int j = 0; j < 8; j++) {
                const int n = n0w + j * 8 + 2 * (ln & 3);
                const float h0 = fmaxf(acc[i][j][0] + sB1[n], 0.f);
                const float h1v = fmaxf(acc[i][j][1] + sB1[n + 1], 0.f);
                const float h2 = fmaxf(acc[i][j][2] + sB1[n], 0.f);
                const float h3 = fmaxf(acc[i][j][3] + sB1[n + 1], 0.f);
                *(uint32_t*)(smem + OFF_A + r0 * (ASTRIDE * 2) + n * 2) = pack_half2(h0, h1v);
                *(uint32_t*)(smem + OFF_A + (r0 + 8) * (ASTRIDE * 2) + n * 2) = pack_half2(h2, h3);
            }
        }
    }
    __syncthreads();

    // ---- phase 2: main single-term HMMA GEMM, 4 K-panels, double-buffered ----
#pragma unroll
    for (int i = 0; i < 4; i++)
#pragma unroll
        for (int j = 0; j < 8; j++)
#pragma unroll
            for (int c = 0; c < 4; c++) acc[i][j][c] = 0.f;

    const uint32_t aBase = sb + OFF_A +
        (uint32_t)((m0w + (ln & 15)) * (ASTRIDE * 2) + (ln >> 4) * 16);
    const int swz = ln & 7;
    const uint32_t bRow = (uint32_t)((n0w + rsel) * 128);

    for (int p = 0; p < 4; p++) {
        if (p < 3) {
            stageB(p + 1, (p + 1) & 1);
            asm volatile("cp.async.wait_group 1;" ::: "memory");
        } else {
            asm volatile("cp.async.wait_group 0;" ::: "memory");
        }
        __syncthreads();

        const uint32_t bBase = sb + OFF_B + (uint32_t)((p & 1) * BUFSZ) + bRow;

#pragma unroll
        for (int ks = 0; ks < 4; ks++) {
            uint32_t ah[4][4], bh[4][4];
            const uint32_t ka = (uint32_t)(p * 128 + ks * 32);
#pragma unroll
            for (int i = 0; i < 4; i++)
                ldsm4(ah[i], aBase + ka + (uint32_t)(i * 16 * ASTRIDE * 2));
            const uint32_t bchunk = (uint32_t)(((ks * 2 + cpart) ^ swz) << 4);
#pragma unroll
            for (int jj = 0; jj < 4; jj++)
                ldsm4(bh[jj], bBase + bchunk + (uint32_t)(jj * 16 * 128));
#pragma unroll
            for (int jj = 0; jj < 4; jj++)
#pragma unroll
                for (int i = 0; i < 4; i++) {
                    mma16816(acc[i][2 * jj],     ah[i], bh[jj][0], bh[jj][1]);
                    mma16816(acc[i][2 * jj + 1], ah[i], bh[jj][2], bh[jj][3]);
                }
        }
        __syncthreads();
    }

    // ---- epilogue: h2 = acc + b2; relu; dot Wout; reduce ----
    float po[4][2] = {{0.f, 0.f}, {0.f, 0.f}, {0.f, 0.f}, {0.f, 0.f}};
#pragma unroll
    for (int i = 0; i < 4; i++)
#pragma unroll
        for (int j = 0; j < 8; j++) {
            const int nb = n0w + j * 8 + 2 * (ln & 3);
            const float2 bw0 = sBW[nb], bw1 = sBW[nb + 1];
            po[i][0] += fmaxf(acc[i][j][0] + bw0.x, 0.f) * bw0.y
                      + fmaxf(acc[i][j][1] + bw1.x, 0.f) * bw1.y;
            po[i][1] += fmaxf(acc[i][j][2] + bw0.x, 0.f) * bw0.y
                      + fmaxf(acc[i][j][3] + bw1.x, 0.f) * bw1.y;
        }
#pragma unroll
    for (int o = 1; o <= 2; o <<= 1)
#pragma unroll
        for (int i = 0; i < 4; i++) {
            po[i][0] += __shfl_xor_sync(0xffffffffu, po[i][0], o);
            po[i][1] += __shfl_xor_sync(0xffffffffu, po[i][1], o);
        }
    if ((ln & 3) == 0) {
        const int r = ln >> 2;
#pragma unroll
        for (int i = 0; i < 4; i++) {
            atomicAdd(&sred[m0w + i * 16 + r], po[i][0]);
            atomicAdd(&sred[m0w + i * 16 + 8 + r], po[i][1]);
        }
    }
    __syncthreads();
    if (tid < MT_) out[b * T_ + tid] = sred[tid] + bout[0];
}

extern "C" void kernel_launch(void* const* d_in, const int* in_sizes, int n_in,
                              void* d_out, int out_size) {
    const float* state  = (const float*)d_in[0];
    const float* action = (const float*)d_in[1];
    const float* Wk     = (const float*)d_in[2];
    const float* Wq     = (const float*)d_in[3];
    const float* Wv     = (const float*)d_in[4];
    const float* W1     = (const float*)d_in[5];
    const float* b1     = (const float*)d_in[6];
    const float* W2     = (const float*)d_in[7];
    const float* b2     = (const float*)d_in[8];
    const float* Wout   = (const float*)d_in[9];
    const float* bout   = (const float*)d_in[10];
    float* out = (float*)d_out;

    const int smem = MT_ * ASTRIDE * 2          // A tile          67584
                   + 2 * (HID_ * KP_ * 2)       // B double buffer 65536
                   + 16384                      // W1 tile (fp16)
                   + 8192                       // feat tile (fp16)
                   + 2048 + 1024 + 512;         // bw, b1, red     -> 161280
    cudaFuncSetAttribute(fused_kernel, cudaFuncAttributeMaxDynamicSharedMemorySize, smem);

    wsplit_kernel<<<64, 256>>>(W2, W1);
    fused_kernel<<<B_, 256, smem>>>(state, action, Wk, Wq, Wv,
                                    b1, b2, Wout, bout, out);
}